// round 14
// baseline (speedup 1.0000x reference)
#include <cuda_runtime.h>
#include <cuda_fp16.h>
#include <math.h>
#include <stdint.h>

#define NMAXT 3329      // 1024 query + 1 sep + 2304 max prompts (logical)
#define NPAD  3344      // token-dim padding
#define SLD   3344      // score-matrix row stride
#define GPTS  2304
#define NBATCH 4

// transposed-half-weight scratch layout (element offsets)
#define WOFF_QKV  0LL                    // 2 x [3072][1024]
#define WOFF_PROJ 6291456LL              // 2 x [1024][1024]
#define WOFF_M1   8388608LL              // 2 x [4096][1024]
#define WOFF_M2   16777216LL             // 2 x [1024][4096]
#define WOFF_W2   25165824LL             // [1024][512]
#define WC_TOTAL  25690112LL

// gemm_h: 3-stage ring, per-stage = 2560 A-words + 2560 B-words
#define GH_STGW  5120
#define GH_SMEM  (3 * GH_STGW * 4)       // 61440 bytes

// ---------------- static device scratch (zero-initialized, never freed) ---------
__device__ int    g_M[NBATCH];
__device__ int    g_rows[NBATCH*GPTS];
__device__ int    g_cols[NBATCH*GPTS];
__device__ float  g_X   [(size_t)NBATCH*NPAD*1024];            // residual, fp32
__device__ __half g_Yh  [(size_t)NBATCH*NPAD*1024];            // LN out / attn out
__device__ __half g_QKVh[(size_t)NBATCH*NPAD*3072];            // pad rows stay 0
__device__ __half g_Sh  [(size_t)NBATCH*4*NPAD*SLD];           // logits->probs, pad 0
__device__ __half g_Hh  [(size_t)NBATCH*NPAD*4096];            // MLP hidden
__device__ __half g_Vt  [(size_t)NBATCH*1024*NPAD];            // V transposed [dim][tok]
__device__ float  g_Qpe [1024*1024];
__device__ float  g_Ppe [(size_t)NBATCH*GPTS*1024];
__device__ __half g_Hph [(size_t)NBATCH*GPTS*512];
__device__ float  g_Pft [(size_t)NBATCH*GPTS*1024];
__device__ __half g_Wch [WC_TOTAL];

__device__ __forceinline__ float geluf(float x) {
    return 0.5f * x * (1.0f + erff(x * 0.7071067811865475f));
}
__device__ __forceinline__ float warpSum(float v) {
    #pragma unroll
    for (int o = 16; o; o >>= 1) v += __shfl_xor_sync(0xFFFFFFFFu, v, o);
    return v;
}
__device__ __forceinline__ float warpMax(float v) {
    #pragma unroll
    for (int o = 16; o; o >>= 1) v = fmaxf(v, __shfl_xor_sync(0xFFFFFFFFu, v, o));
    return v;
}

// ---------------- weight transpose fp32[K][N] -> half[N][K] ---------------------
__global__ void wtr_k(const float* __restrict__ src, __half* __restrict__ dst,
                      int K, int N) {
    __shared__ float t[32][33];
    src += (size_t)blockIdx.z * K * N;
    dst += (size_t)blockIdx.z * K * N;
    int n0 = blockIdx.x * 32, k0 = blockIdx.y * 32;
    int tx = threadIdx.x, ty = threadIdx.y;
    #pragma unroll
    for (int i = 0; i < 32; i += 8)
        t[ty + i][tx] = src[(size_t)(k0 + ty + i) * N + n0 + tx];
    __syncthreads();
    #pragma unroll
    for (int i = 0; i < 32; i += 8)
        dst[(size_t)(n0 + ty + i) * K + k0 + tx] = __float2half_rn(t[tx][ty + i]);
}

// ---------------- V transpose half [tok][dim] -> half [dim][tok] ----------------
__global__ void vtr_k(const __half* __restrict__ QKVh, __half* __restrict__ Vt) {
    __shared__ __half t[32][40];
    int b = blockIdx.z;
    const __half* src = QKVh + (size_t)b*NPAD*3072 + 2048;
    __half* dst = Vt + (size_t)b*1024*NPAD;
    int t0 = blockIdx.x * 32, n0 = blockIdx.y * 32;
    int tx = threadIdx.x, ty = threadIdx.y;
    #pragma unroll
    for (int i = 0; i < 32; i += 8) {
        int tt = t0 + ty + i;
        t[ty + i][tx] = (tt < NPAD) ? src[(size_t)tt*3072 + n0 + tx] : __half(0.f);
    }
    __syncthreads();
    #pragma unroll
    for (int i = 0; i < 32; i += 8) {
        int tt = t0 + tx;
        if (tt < NPAD) dst[(size_t)(n0 + ty + i)*NPAD + tt] = t[tx][ty + i];
    }
}

// ---------------- mask compaction (row-major order == np.nonzero) ---------------
__global__ void compact_k(const int* __restrict__ mask) {
    int b = threadIdx.x;
    if (b >= NBATCH) return;
    const int* mb = mask + b * GPTS;
    int cnt = 0;
    for (int i = 0; i < GPTS; i++) {
        if (mb[i] > 0) {
            g_rows[b*GPTS + cnt] = i / 48;
            g_cols[b*GPTS + cnt] = i % 48;
            cnt++;
        }
    }
    g_M[b] = cnt;
}

// ---------------- query positional encoding -------------------------------------
__global__ void qpe_k(const float* __restrict__ gauss) {
    int t = blockIdx.x;            // t = i*32 + j
    int i = t >> 5, j = t & 31;
    float cx = 2.0f * ((j + 0.5f) / 32.0f) - 1.0f;
    float cy = 2.0f * ((i + 0.5f) / 32.0f) - 1.0f;
    for (int k = threadIdx.x; k < 512; k += 256) {
        float ang = 6.283185307179586f * (cx * gauss[k] + cy * gauss[512 + k]);
        g_Qpe[(size_t)t*1024 + k]       = sinf(ang);
        g_Qpe[(size_t)t*1024 + 512 + k] = cosf(ang);
    }
}

// ------------- prompt PE + depth hidden layer gelu(d*w1+b1) ---------------------
__global__ void pembed_k(const float* __restrict__ depth, const float* __restrict__ gauss,
                         const float* __restrict__ w1, const float* __restrict__ b1) {
    int b = blockIdx.y, j = blockIdx.x;
    if (j >= g_M[b]) return;
    int r = g_rows[b*GPTS + j], c = g_cols[b*GPTS + j];
    float cx = 2.0f * ((c + 0.5f) / 48.0f) - 1.0f;
    float cy = 2.0f * ((r + 0.5f) / 48.0f) - 1.0f;
    float d = depth[b*GPTS + r*48 + c];
    size_t base = (size_t)b*GPTS + j;
    for (int k = threadIdx.x; k < 512; k += 256) {
        float ang = 6.283185307179586f * (cx * gauss[k] + cy * gauss[512 + k]);
        g_Ppe[base*1024 + k]       = sinf(ang);
        g_Ppe[base*1024 + 512 + k] = cosf(ang);
        g_Hph[base*512  + k]       = __float2half_rn(geluf(fmaf(d, w1[k], b1[k])));
    }
}

// ---------------- build residual stream (float4) --------------------------------
__global__ void build_x(const float* __restrict__ img, const float* __restrict__ sep0) {
    int b = blockIdx.y, t = blockIdx.x;
    if (t >= 1025 + g_M[b]) return;
    int c = threadIdx.x;                          // 256 threads x float4 = 1024
    float4* x4 = (float4*)(g_X + ((size_t)b*NPAD + t) * 1024);
    if (t < 1024) {
        float4 a = ((const float4*)(img + ((size_t)b*1024 + t) * 1024))[c];
        float4 p = ((const float4*)(g_Qpe + (size_t)t*1024))[c];
        a.x += p.x; a.y += p.y; a.z += p.z; a.w += p.w;
        x4[c] = a;
    } else if (t == 1024) {
        x4[c] = ((const float4*)sep0)[c];
    } else {
        size_t base = (size_t)b*GPTS + (t - 1025);
        float4 a = ((const float4*)(g_Pft + base*1024))[c];
        float4 p = ((const float4*)(g_Ppe + base*1024))[c];
        a.x += p.x; a.y += p.y; a.z += p.z; a.w += p.w;
        x4[c] = a;
    }
}

__global__ void sep_rep(const float* __restrict__ sep1) {
    int b = blockIdx.x;
    float4* x4 = (float4*)(g_X + ((size_t)b*NPAD + 1024) * 1024);
    x4[threadIdx.x] = ((const float4*)sep1)[threadIdx.x];
}

// ---------------- layernorm: fp32 in -> half out --------------------------------
__global__ void ln_k(const float* __restrict__ Xin, __half* __restrict__ Yout,
                     const float* __restrict__ w, const float* __restrict__ bb) {
    int b = blockIdx.y, t = blockIdx.x;
    if (t >= 1025 + g_M[b]) return;
    int tid = threadIdx.x;
    const float4* x4 = (const float4*)(Xin + ((size_t)b*NPAD + t) * 1024);
    float4 v = x4[tid];
    float s  = v.x + v.y + v.z + v.w;
    float sq = v.x*v.x + v.y*v.y + v.z*v.z + v.w*v.w;
    __shared__ float shs[8], shq[8], res[2];
    float ws = warpSum(s), wq = warpSum(sq);
    if ((tid & 31) == 0) { shs[tid>>5] = ws; shq[tid>>5] = wq; }
    __syncthreads();
    if (tid == 0) {
        float a = 0.f, q = 0.f;
        #pragma unroll
        for (int i = 0; i < 8; i++) { a += shs[i]; q += shq[i]; }
        res[0] = a; res[1] = q;
    }
    __syncthreads();
    float mean = res[0] * (1.0f/1024.0f);
    float var  = res[1] * (1.0f/1024.0f) - mean*mean;
    float rstd = rsqrtf(var + 1e-5f);
    float4 wv = ((const float4*)w)[tid];
    float4 bv = ((const float4*)bb)[tid];
    __half2* yrow = (__half2*)(Yout + ((size_t)b*NPAD + t) * 1024);
    yrow[2*tid]   = __floats2half2_rn((v.x - mean)*rstd*wv.x + bv.x,
                                      (v.y - mean)*rstd*wv.y + bv.y);
    yrow[2*tid+1] = __floats2half2_rn((v.z - mean)*rstd*wv.z + bv.z,
                                      (v.w - mean)*rstd*wv.w + bv.w);
}

// ---------------- row softmax: half logits -> half probs, half2 vectorized ------
__global__ void softmax_k() {
    int z = blockIdx.y;            // b*4 + head
    int b = z >> 2;
    int Nd = 1025 + g_M[b];
    int row = blockIdx.x;
    if (row >= Nd) return;
    __half2* sh2 = (__half2*)(g_Sh + (size_t)z*NPAD*SLD + (size_t)row*SLD);
    int tid = threadIdx.x;
    __shared__ float red[8];

    // 7 half2 per thread: 256*7*2 = 3584 >= SLD
    float2 vals[7];
    float m = -3.4e38f;
    #pragma unroll
    for (int t = 0; t < 7; t++) {
        int j2 = tid + t*256;
        int c0 = j2 << 1;
        if (c0 < Nd) {
            float2 v = __half22float2(sh2[j2]);
            vals[t] = v;
            m = fmaxf(m, v.x);
            if (c0 + 1 < Nd) m = fmaxf(m, v.y);
        }
    }
    m = warpMax(m);
    if ((tid & 31) == 0) red[tid>>5] = m;
    __syncthreads();
    if (tid == 0) {
        float v = red[0];
        #pragma unroll
        for (int i = 1; i < 8; i++) v = fmaxf(v, red[i]);
        red[0] = v;
    }
    __syncthreads();
    m = red[0];
    __syncthreads();

    float sum = 0.f;
    #pragma unroll
    for (int t = 0; t < 7; t++) {
        int j2 = tid + t*256;
        int c0 = j2 << 1;
        if (c0 < Nd) {
            float e0 = expf(vals[t].x - m);
            float e1 = (c0 + 1 < Nd) ? expf(vals[t].y - m) : 0.f;
            vals[t].x = e0; vals[t].y = e1;
            sum += e0 + e1;
        }
    }
    sum = warpSum(sum);
    if ((tid & 31) == 0) red[tid>>5] = sum;
    __syncthreads();
    if (tid == 0) {
        float v = 0.f;
        #pragma unroll
        for (int i = 0; i < 8; i++) v += red[i];
        red[0] = v;
    }
    __syncthreads();
    float inv = 1.0f / red[0];
    #pragma unroll
    for (int t = 0; t < 7; t++) {
        int j2 = tid + t*256;
        int c0 = j2 << 1;
        if (c0 + 1 < Nd) {
            sh2[j2] = __floats2half2_rn(vals[t].x * inv, vals[t].y * inv);
        } else if (c0 < Nd) {
            // odd tail: keep pad column exactly 0
            ((__half*)sh2)[c0] = __float2half_rn(vals[t].x * inv);
        }
    }
}

// ================= shared GEMM helpers ==========================================
__device__ __forceinline__ int dimval(int st, int dyn, int b) {
    if (dyn == 1) return 1025 + g_M[b];
    if (dyn == 2) return g_M[b];
    return st;
}
__device__ __forceinline__ void cpa16(uint32_t dst, const void* src, int srcBytes) {
    asm volatile("cp.async.cg.shared.global [%0], [%1], 16, %2;"
                 :: "r"(dst), "l"(src), "r"(srcBytes));
}
#define MMA_F16(d, a, bq)                                                \
    asm volatile("mma.sync.aligned.m16n8k16.row.col.f32.f16.f16.f32 "    \
        "{%0,%1,%2,%3},{%4,%5,%6,%7},{%8,%9},{%0,%1,%2,%3};"             \
        : "+f"(d[0]),"+f"(d[1]),"+f"(d[2]),"+f"(d[3])                    \
        : "r"(a[0]),"r"(a[1]),"r"(a[2]),"r"(a[3]),"r"(bq[0]),"r"(bq[1]))
#define LDSM4(r0, r1, r2, r3, addr)                                      \
    asm volatile("ldmatrix.sync.aligned.m8n8.x4.shared.b16 "             \
        "{%0,%1,%2,%3}, [%4];"                                           \
        : "=r"(r0), "=r"(r1), "=r"(r2), "=r"(r3) : "r"(addr))
#define LDSM2(r0, r1, addr)                                              \
    asm volatile("ldmatrix.sync.aligned.m8n8.x2.shared.b16 "             \
        "{%0,%1}, [%2];"                                                 \
        : "=r"(r0), "=r"(r1) : "r"(addr))

// =========================== fp16 tensor-core GEMM ==============================
// C = alpha * A @ B^T (+bias)(+gelu)(+=C fp32)(OUTH: half store)
// A: half [M][K] row-major; B: half [N][K] row-major.
// 128x128x32 CTA tile, 8 warps (2x4), 64x32 warp tile, m16n8k16 f16 mma,
// 3-stage cp.async ring (dynamic smem), ldmatrix fragment loads.
template<int EPI, bool ACCUM, bool OUTH>
__global__ void __launch_bounds__(256, 2) gemm_h(
    const __half* __restrict__ A, long long aOut, long long aIn, int lda,
    const __half* __restrict__ B, long long bOut, long long bIn, int ldb,
    void* __restrict__ Cv, long long cOut, long long cIn, int ldc,
    const float* __restrict__ bias,
    int nInner, int Mst, int Nst, int Kst,
    int dynM, int dynN, int dynK, float alpha)
{
    int z = blockIdx.z;
    int b = z / nInner, ii = z - b*nInner;
    int Mr = dimval(Mst, dynM, b);
    int Nc = dimval(Nst, dynN, b);
    int K  = dimval(Kst, dynK, b);
    int Kpad = (K + 31) & ~31;
    int m0 = blockIdx.y * 128, n0 = blockIdx.x * 128;
    if (m0 >= Mr || n0 >= Nc) return;
    A += b*aOut + ii*aIn;
    B += b*bOut + ii*bIn;

    extern __shared__ __align__(16) uint32_t smw[];
    uint32_t sBase = (uint32_t)__cvta_generic_to_shared(smw);

    int tid  = threadIdx.x;
    int wid  = tid >> 5, lane = tid & 31;
    int wm   = (wid >> 2) * 64;
    int wn   = (wid & 3) * 32;
    int g    = lane >> 2, t4 = lane & 3;

    float acc[4][4][4];
    #pragma unroll
    for (int i = 0; i < 4; i++)
        #pragma unroll
        for (int j = 0; j < 4; j++)
            #pragma unroll
            for (int e = 0; e < 4; e++) acc[i][j][e] = 0.f;

    // per stage: A at word 0, B at word 2560 (stage stride GH_STGW words)
    auto issue = [&](int kt, int stg) {
        int k0 = kt << 5;
        uint32_t sA = sBase + (uint32_t)(stg*GH_STGW)*4;
        uint32_t sB = sA + 2560u*4;
        #pragma unroll
        for (int i = 0; i < 2; i++) {
            int idx = tid + 256*i;
            int r = idx >> 2, cw = (idx & 3) << 2;
            int gm = m0 + r;
            bool ok = gm < Mr;
            const __half* src = ok ? (A + (long long)gm*lda + k0 + (cw<<1)) : A;
            cpa16(sA + (uint32_t)(r*20 + cw)*4, src, ok ? 16 : 0);
        }
        #pragma unroll
        for (int i = 0; i < 2; i++) {
            int idx = tid + 256*i;
            int r = idx >> 2, cw = (idx & 3) << 2;
            int gn = n0 + r;
            bool ok = gn < Nc;
            const __half* src = ok ? (B + (long long)gn*ldb + k0 + (cw<<1)) : B;
            cpa16(sB + (uint32_t)(r*20 + cw)*4, src, ok ? 16 : 0);
        }
    };

    int lane16 = lane & 15;
    int laneh  = lane >> 4;
    int lane8  = lane & 7;
    int laneb  = (lane >> 3) & 1;

    auto compute = [&](int stg) {
        uint32_t sA = sBase + (uint32_t)(stg*GH_STGW)*4;
        uint32_t sB = sA + 2560u*4;
        uint32_t aBase = sA + (uint32_t)((wm + lane16)*20 + laneh*4)*4;
        uint32_t bBase = sB + (uint32_t)((wn + lane8 )*20 + laneb*4)*4;
        #pragma unroll
        for (int ks = 0; ks < 2; ks++) {
            uint32_t kOff = (uint32_t)(ks*8)*4;
            uint32_t af[4][4], bf[4][2];
            #pragma unroll
            for (int mf = 0; mf < 4; mf++)
                LDSM4(af[mf][0], af[mf][1], af[mf][2], af[mf][3],
                      aBase + (uint32_t)(mf*16*20)*4 + kOff);
            #pragma unroll
            for (int nf = 0; nf < 4; nf++)
                LDSM2(bf[nf][0], bf[nf][1],
                      bBase + (uint32_t)(nf*8*20)*4 + kOff);
            #pragma unroll
            for (int mf = 0; mf < 4; mf++)
                #pragma unroll
                for (int nf = 0; nf < 4; nf++)
                    MMA_F16(acc[mf][nf], af[mf], bf[nf]);
        }
    };

    int ntiles = Kpad >> 5;
    // prologue: stages 0,1
    issue(0, 0);
    asm volatile("cp.async.commit_group;" ::: "memory");
    if (ntiles > 1) issue(1, 1);
    asm volatile("cp.async.commit_group;" ::: "memory");

    int stg = 0, nxt = 2;                 // nxt = (it+2) % 3 ring slot
    for (int it = 0; it < ntiles; it++) {
        asm volatile("cp.async.wait_group 1;" ::: "memory");
        __syncthreads();
        if (it + 2 < ntiles) issue(it + 2, nxt);
        asm volatile("cp.async.commit_group;" ::: "memory");
        compute(stg);
        __syncthreads();
        stg = (stg == 2) ? 0 : stg + 1;
        nxt = (nxt == 2) ? 0 : nxt + 1;
    }

    float*  Cf = (float*) Cv;
    __half* Ch = (__half*)Cv;
    long long cbase = b*cOut + ii*cIn;
    #pragma unroll
    for (int mf = 0; mf < 4; mf++) {
        #pragma unroll
        for (int nf = 0; nf < 4; nf++) {
            int gn0 = n0 + wn + nf*8 + 2*t4;
            #pragma unroll
            for (int rr = 0; rr < 2; rr++) {
                int gm = m0 + wm + mf*16 + g + rr*8;
                if (gm >= Mr) continue;
                float v0 = acc[mf][nf][2*rr    ] * alpha;
                float v1 = acc[mf][nf][2*rr + 1] * alpha;
                if (bias) { v0 += bias[gn0]; v1 += bias[gn0 + 1]; }
                if (EPI == 1) { v0 = geluf(v0); v1 = geluf(v1); }
                long long off = cbase + (long long)gm*ldc + gn0;
                if (OUTH) {
                    if (gn0 + 1 < Nc)
                        *(__half2*)(Ch + off) = __floats2half2_rn(v0, v1);
                    else if (gn0 < Nc)
                        Ch[off] = __float2half_rn(v0);
                } else {
                    if (gn0 < Nc)     { if (ACCUM) Cf[off]   += v0; else Cf[off]   = v0; }
                    if (gn0 + 1 < Nc) { if (ACCUM) Cf[off+1] += v1; else Cf[off+1] = v1; }
                }
            }
        }
    }
}

// ---------------- output (float4) ------------------------------------------------
__global__ void out_k(const float* __restrict__ img, float* __restrict__ out) {
    int b = blockIdx.y, t = blockIdx.x;
    const float4* src = (g_M[b] == 0)
        ? (const float4*)(img + ((size_t)b*1024 + t) * 1024)
        : (const float4*)(g_X + ((size_t)b*NPAD + t) * 1024);
    float4* o = (float4*)(out + ((size_t)b*1024 + t) * 1024);
    o[threadIdx.x] = src[threadIdx.x];
}

// ================================ host ==========================================
extern "C" void kernel_launch(void* const* d_in, const int* in_sizes, int n_in,
                              void* d_out, int out_size) {
    const float* img   = (const float*)d_in[0];
    const float* depth = (const float*)d_in[1];
    const int*   mask  = (const int*)  d_in[2];
    const float* gauss = (const float*)d_in[5];
    const float* w1    = (const float*)d_in[6];
    const float* b1    = (const float*)d_in[7];
    const float* w2    = (const float*)d_in[8];
    const float* b2    = (const float*)d_in[9];
    const float* sep   = (const float*)d_in[10];
    const float* ln1w  = (const float*)d_in[11];
    const float* ln1b  = (const float*)d_in[12];
    const float* qkvw  = (const float*)d_in[13];
    const float* qkvb  = (const float*)d_in[14];
    const float* projw = (const float*)d_in[15];
    const float* projb = (const float*)d_in[16];
    const float* ln2w  = (const float*)d_in[17];
    const float* ln2b  = (const float*)d_in[18];
    const float* m1w   = (const float*)d_in[19];
    const float* m1b   = (const float*)d_in[20];
    const float* m2w   = (const float*)d_in[21];
    const float* m2b   = (const float*)d_in[22];
    float* out = (float*)d_out;

    // 60KB dynamic smem for all gemm_h instantiations (idempotent host calls)
    cudaFuncSetAttribute(gemm_h<0,false,false>,
        cudaFuncAttributeMaxDynamicSharedMemorySize, GH_SMEM);
    cudaFuncSetAttribute(gemm_h<0,false,true>,
        cudaFuncAttributeMaxDynamicSharedMemorySize, GH_SMEM);
    cudaFuncSetAttribute(gemm_h<0,true,false>,
        cudaFuncAttributeMaxDynamicSharedMemorySize, GH_SMEM);
    cudaFuncSetAttribute(gemm_h<1,false,true>,
        cudaFuncAttributeMaxDynamicSharedMemorySize, GH_SMEM);

    float *pX, *pPft;
    __half *pYh, *pQKVh, *pSh, *pHh, *pVt, *pHph, *pWch;
    cudaGetSymbolAddress((void**)&pX,    g_X);
    cudaGetSymbolAddress((void**)&pPft,  g_Pft);
    cudaGetSymbolAddress((void**)&pYh,   g_Yh);
    cudaGetSymbolAddress((void**)&pQKVh, g_QKVh);
    cudaGetSymbolAddress((void**)&pSh,   g_Sh);
    cudaGetSymbolAddress((void**)&pHh,   g_Hh);
    cudaGetSymbolAddress((void**)&pVt,   g_Vt);
    cudaGetSymbolAddress((void**)&pHph,  g_Hph);
    cudaGetSymbolAddress((void**)&pWch,  g_Wch);

    const long long SX   = (long long)NPAD * 1024;
    const long long SQKV = (long long)NPAD * 3072;
    const long long SH   = (long long)NPAD * 4096;
    const long long SS1  = (long long)NPAD * SLD;    // per head
    const long long SSB  = 4LL * SS1;                // per batch

    // --- transpose+round all GEMM weights to half [N][K] once per call ---
    {
        dim3 blk(32, 8);
        wtr_k<<<dim3(96, 32, 2),  blk>>>(qkvw,  pWch + WOFF_QKV,  1024, 3072);
        wtr_k<<<dim3(32, 32, 2),  blk>>>(projw, pWch + WOFF_PROJ, 1024, 1024);
        wtr_k<<<dim3(128, 32, 2), blk>>>(m1w,   pWch + WOFF_M1,   1024, 4096);
        wtr_k<<<dim3(32, 128, 2), blk>>>(m2w,   pWch + WOFF_M2,   4096, 1024);
        wtr_k<<<dim3(32, 16, 1),  blk>>>(w2,    pWch + WOFF_W2,    512, 1024);
    }
    const __half* qkvT  = pWch + WOFF_QKV;
    const __half* projT = pWch + WOFF_PROJ;
    const __half* m1T   = pWch + WOFF_M1;
    const __half* m2T   = pWch + WOFF_M2;
    const __half* w2T   = pWch + WOFF_W2;

    compact_k<<<1, NBATCH>>>(mask);
    qpe_k<<<1024, 256>>>(gauss);
    pembed_k<<<dim3(GPTS, NBATCH), 256>>>(depth, gauss, w1, b1);

    // prompt features: Pft = Hp @ w2 + b2 (rows = g_M[b]) -> fp32 (feeds X)
    gemm_h<0,false,false><<<dim3(8, 18, NBATCH), 256, GH_SMEM>>>(
        pHph, (long long)GPTS*512, 0, 512,
        w2T, 0, 0, 512,
        pPft, (long long)GPTS*1024, 0, 1024,
        b2, 1, 0, 1024, 512, 2, 0, 0, 1.0f);

    build_x<<<dim3(NMAXT, NBATCH), 256>>>(img, sep);

    for (int i = 0; i < 2; i++) {
        if (i) sep_rep<<<NBATCH, 256>>>(sep + (size_t)i*1024);

        ln_k<<<dim3(NMAXT, NBATCH), 256>>>(pX, pYh, ln1w + i*1024, ln1b + i*1024);

        // QKV = Y @ qkv_w + qkv_b  -> half
        gemm_h<0,false,true><<<dim3(24, 27, NBATCH), 256, GH_SMEM>>>(
            pYh, SX, 0, 1024,
            qkvT + (size_t)i*3072*1024, 0, 0, 1024,
            pQKVh, SQKV, 0, 3072,
            qkvb + (size_t)i*3072, 1, 0, 3072, 1024, 1, 0, 0, 1.0f);

        // V transpose for S@V B-operand
        vtr_k<<<dim3(105, 32, NBATCH), dim3(32, 8)>>>(pQKVh, pVt);

        // S = Q K^T / 16 -> half logits directly (per head, z = b*4+h)
        gemm_h<0,false,true><<<dim3(27, 27, NBATCH*4), 256, GH_SMEM>>>(
            pQKVh, SQKV, 256, 3072,
            pQKVh + 1024, SQKV, 256, 3072,
            pSh, SSB, SS1, SLD,
            nullptr, 4, 0, 0, 256, 1, 1, 0, 0.0625f);

        softmax_k<<<dim3(NMAXT, NBATCH*4), 256>>>();

        // O = Sh @ Vt^T -> Yh half (per-head column slice)
        gemm_h<0,false,true><<<dim3(2, 27, NBATCH*4), 256, GH_SMEM>>>(
            pSh, SSB, SS1, SLD,
            pVt, (long long)1024*NPAD, (long long)256*NPAD, NPAD,
            pYh, SX, 256, 1024,
            nullptr, 4, 0, 256, 0, 1, 0, 1, 1.0f);

        // X += O @ proj_w + proj_b  (residual fp32)
        gemm_h<0,true,false><<<dim3(8, 27, NBATCH), 256, GH_SMEM>>>(
            pYh, SX, 0, 1024,
            projT + (size_t)i*1024*1024, 0, 0, 1024,
            pX, SX, 0, 1024,
            projb + (size_t)i*1024, 1, 0, 1024, 1024, 1, 0, 0, 1.0f);

        ln_k<<<dim3(NMAXT, NBATCH), 256>>>(pX, pYh, ln2w + i*1024, ln2b + i*1024);

        // H = gelu(Y @ mlp_w1 + mlp_b1) -> half
        gemm_h<1,false,true><<<dim3(32, 27, NBATCH), 256, GH_SMEM>>>(
            pYh, SX, 0, 1024,
            m1T + (size_t)i*4096*1024, 0, 0, 1024,
            pHh, SH, 0, 4096,
            m1b + (size_t)i*4096, 1, 0, 4096, 1024, 1, 0, 0, 1.0f);

        // X += H @ mlp_w2 + mlp_b2  (residual fp32)
        gemm_h<0,true,false><<<dim3(8, 27, NBATCH), 256, GH_SMEM>>>(
            pHh, SH, 0, 4096,
            m2T + (size_t)i*1024*4096, 0, 0, 4096,
            pX, SX, 0, 1024,
            m2b + (size_t)i*1024, 1, 0, 1024, 4096, 1, 0, 0, 1.0f);
    }

    out_k<<<dim3(1024, NBATCH), 256>>>(img, out);
}

// round 15
// speedup vs baseline: 1.0548x; 1.0548x over previous
#include <cuda_runtime.h>
#include <cuda_fp16.h>
#include <math.h>
#include <stdint.h>

#define NMAXT 3329      // 1024 query + 1 sep + 2304 max prompts (logical)
#define NPAD  3344      // token-dim padding
#define SLD   3344      // score-matrix row stride
#define GPTS  2304
#define NBATCH 4

// transposed-half-weight scratch layout (element offsets)
#define WOFF_QKV  0LL                    // 2 x [3072][1024]
#define WOFF_PROJ 6291456LL              // 2 x [1024][1024]
#define WOFF_M1   8388608LL              // 2 x [4096][1024]
#define WOFF_M2   16777216LL             // 2 x [1024][4096]
#define WOFF_W2   25165824LL             // [1024][512]
#define WC_TOTAL  25690112LL

// ---------------- static device scratch (zero-initialized, never freed) ---------
__device__ int    g_M[NBATCH];
__device__ int    g_rows[NBATCH*GPTS];
__device__ int    g_cols[NBATCH*GPTS];
__device__ float  g_X   [(size_t)NBATCH*NPAD*1024];            // residual, fp32
__device__ __half g_Yh  [(size_t)NBATCH*NPAD*1024];            // LN out / attn out
__device__ __half g_QKVh[(size_t)NBATCH*NPAD*3072];            // pad rows stay 0
__device__ __half g_Sh  [(size_t)NBATCH*4*NPAD*SLD];           // logits->probs, pad 0
__device__ __half g_Hh  [(size_t)NBATCH*NPAD*4096];            // MLP hidden
__device__ __half g_Vt  [(size_t)NBATCH*1024*NPAD];            // V transposed [dim][tok]
__device__ float  g_Qpe [1024*1024];
__device__ float  g_Ppe [(size_t)NBATCH*GPTS*1024];
__device__ __half g_Hph [(size_t)NBATCH*GPTS*512];
__device__ float  g_Pft [(size_t)NBATCH*GPTS*1024];
__device__ __half g_Wch [WC_TOTAL];

__device__ __forceinline__ float geluf(float x) {
    return 0.5f * x * (1.0f + erff(x * 0.7071067811865475f));
}
__device__ __forceinline__ float warpSum(float v) {
    #pragma unroll
    for (int o = 16; o; o >>= 1) v += __shfl_xor_sync(0xFFFFFFFFu, v, o);
    return v;
}
__device__ __forceinline__ float warpMax(float v) {
    #pragma unroll
    for (int o = 16; o; o >>= 1) v = fmaxf(v, __shfl_xor_sync(0xFFFFFFFFu, v, o));
    return v;
}

// ---------------- weight transpose fp32[K][N] -> half[N][K] ---------------------
__global__ void wtr_k(const float* __restrict__ src, __half* __restrict__ dst,
                      int K, int N) {
    __shared__ float t[32][33];
    src += (size_t)blockIdx.z * K * N;
    dst += (size_t)blockIdx.z * K * N;
    int n0 = blockIdx.x * 32, k0 = blockIdx.y * 32;
    int tx = threadIdx.x, ty = threadIdx.y;
    #pragma unroll
    for (int i = 0; i < 32; i += 8)
        t[ty + i][tx] = src[(size_t)(k0 + ty + i) * N + n0 + tx];
    __syncthreads();
    #pragma unroll
    for (int i = 0; i < 32; i += 8)
        dst[(size_t)(n0 + ty + i) * K + k0 + tx] = __float2half_rn(t[tx][ty + i]);
}

// ---------------- V transpose half [tok][dim] -> half [dim][tok] ----------------
__global__ void vtr_k(const __half* __restrict__ QKVh, __half* __restrict__ Vt) {
    __shared__ __half t[32][40];
    int b = blockIdx.z;
    const __half* src = QKVh + (size_t)b*NPAD*3072 + 2048;
    __half* dst = Vt + (size_t)b*1024*NPAD;
    int t0 = blockIdx.x * 32, n0 = blockIdx.y * 32;
    int tx = threadIdx.x, ty = threadIdx.y;
    #pragma unroll
    for (int i = 0; i < 32; i += 8) {
        int tt = t0 + ty + i;
        t[ty + i][tx] = (tt < NPAD) ? src[(size_t)tt*3072 + n0 + tx] : __half(0.f);
    }
    __syncthreads();
    #pragma unroll
    for (int i = 0; i < 32; i += 8) {
        int tt = t0 + tx;
        if (tt < NPAD) dst[(size_t)(n0 + ty + i)*NPAD + tt] = t[tx][ty + i];
    }
}

// ------- mask compaction: parallel block scan, order == np.nonzero --------------
// one block per batch; thread t owns contiguous elements [t*9, t*9+9)
__global__ void compact_k(const int* __restrict__ mask) {
    int b = blockIdx.x;
    const int* mb = mask + b * GPTS;
    int tid = threadIdx.x, lane = tid & 31, w = tid >> 5;
    __shared__ int warpTot[8], warpBase[8];

    int flags[9];
    int cnt = 0;
    int base0 = tid * 9;
    #pragma unroll
    for (int j = 0; j < 9; j++) {
        flags[j] = (mb[base0 + j] > 0) ? 1 : 0;
        cnt += flags[j];
    }
    // inclusive warp scan of cnt
    int ws = cnt;
    #pragma unroll
    for (int o = 1; o < 32; o <<= 1) {
        int v = __shfl_up_sync(0xFFFFFFFFu, ws, o);
        if (lane >= o) ws += v;
    }
    if (lane == 31) warpTot[w] = ws;
    __syncthreads();
    if (tid == 0) {
        int acc = 0;
        #pragma unroll
        for (int i = 0; i < 8; i++) { warpBase[i] = acc; acc += warpTot[i]; }
        g_M[b] = acc;
    }
    __syncthreads();
    int pos = warpBase[w] + ws - cnt;        // exclusive prefix for this thread
    #pragma unroll
    for (int j = 0; j < 9; j++) {
        if (flags[j]) {
            int idx = base0 + j;
            g_rows[b*GPTS + pos] = idx / 48;
            g_cols[b*GPTS + pos] = idx % 48;
            pos++;
        }
    }
}

// ---------------- query positional encoding -------------------------------------
__global__ void qpe_k(const float* __restrict__ gauss) {
    int t = blockIdx.x;            // t = i*32 + j
    int i = t >> 5, j = t & 31;
    float cx = 2.0f * ((j + 0.5f) / 32.0f) - 1.0f;
    float cy = 2.0f * ((i + 0.5f) / 32.0f) - 1.0f;
    for (int k = threadIdx.x; k < 512; k += 256) {
        float ang = 6.283185307179586f * (cx * gauss[k] + cy * gauss[512 + k]);
        g_Qpe[(size_t)t*1024 + k]       = sinf(ang);
        g_Qpe[(size_t)t*1024 + 512 + k] = cosf(ang);
    }
}

// ------------- prompt PE + depth hidden layer gelu(d*w1+b1) ---------------------
__global__ void pembed_k(const float* __restrict__ depth, const float* __restrict__ gauss,
                         const float* __restrict__ w1, const float* __restrict__ b1) {
    int b = blockIdx.y, j = blockIdx.x;
    if (j >= g_M[b]) return;
    int r = g_rows[b*GPTS + j], c = g_cols[b*GPTS + j];
    float cx = 2.0f * ((c + 0.5f) / 48.0f) - 1.0f;
    float cy = 2.0f * ((r + 0.5f) / 48.0f) - 1.0f;
    float d = depth[b*GPTS + r*48 + c];
    size_t base = (size_t)b*GPTS + j;
    for (int k = threadIdx.x; k < 512; k += 256) {
        float ang = 6.283185307179586f * (cx * gauss[k] + cy * gauss[512 + k]);
        g_Ppe[base*1024 + k]       = sinf(ang);
        g_Ppe[base*1024 + 512 + k] = cosf(ang);
        g_Hph[base*512  + k]       = __float2half_rn(geluf(fmaf(d, w1[k], b1[k])));
    }
}

// ---------------- build residual stream (float4) --------------------------------
__global__ void build_x(const float* __restrict__ img, const float* __restrict__ sep0) {
    int b = blockIdx.y, t = blockIdx.x;
    if (t >= 1025 + g_M[b]) return;
    int c = threadIdx.x;                          // 256 threads x float4 = 1024
    float4* x4 = (float4*)(g_X + ((size_t)b*NPAD + t) * 1024);
    if (t < 1024) {
        float4 a = ((const float4*)(img + ((size_t)b*1024 + t) * 1024))[c];
        float4 p = ((const float4*)(g_Qpe + (size_t)t*1024))[c];
        a.x += p.x; a.y += p.y; a.z += p.z; a.w += p.w;
        x4[c] = a;
    } else if (t == 1024) {
        x4[c] = ((const float4*)sep0)[c];
    } else {
        size_t base = (size_t)b*GPTS + (t - 1025);
        float4 a = ((const float4*)(g_Pft + base*1024))[c];
        float4 p = ((const float4*)(g_Ppe + base*1024))[c];
        a.x += p.x; a.y += p.y; a.z += p.z; a.w += p.w;
        x4[c] = a;
    }
}

__global__ void sep_rep(const float* __restrict__ sep1) {
    int b = blockIdx.x;
    float4* x4 = (float4*)(g_X + ((size_t)b*NPAD + 1024) * 1024);
    x4[threadIdx.x] = ((const float4*)sep1)[threadIdx.x];
}

// ---------------- layernorm: fp32 in -> half out --------------------------------
__global__ void ln_k(const float* __restrict__ Xin, __half* __restrict__ Yout,
                     const float* __restrict__ w, const float* __restrict__ bb) {
    int b = blockIdx.y, t = blockIdx.x;
    if (t >= 1025 + g_M[b]) return;
    int tid = threadIdx.x;
    const float4* x4 = (const float4*)(Xin + ((size_t)b*NPAD + t) * 1024);
    float4 v = x4[tid];
    float s  = v.x + v.y + v.z + v.w;
    float sq = v.x*v.x + v.y*v.y + v.z*v.z + v.w*v.w;
    __shared__ float shs[8], shq[8], res[2];
    float ws = warpSum(s), wq = warpSum(sq);
    if ((tid & 31) == 0) { shs[tid>>5] = ws; shq[tid>>5] = wq; }
    __syncthreads();
    if (tid == 0) {
        float a = 0.f, q = 0.f;
        #pragma unroll
        for (int i = 0; i < 8; i++) { a += shs[i]; q += shq[i]; }
        res[0] = a; res[1] = q;
    }
    __syncthreads();
    float mean = res[0] * (1.0f/1024.0f);
    float var  = res[1] * (1.0f/1024.0f) - mean*mean;
    float rstd = rsqrtf(var + 1e-5f);
    float4 wv = ((const float4*)w)[tid];
    float4 bv = ((const float4*)bb)[tid];
    __half2* yrow = (__half2*)(Yout + ((size_t)b*NPAD + t) * 1024);
    yrow[2*tid]   = __floats2half2_rn((v.x - mean)*rstd*wv.x + bv.x,
                                      (v.y - mean)*rstd*wv.y + bv.y);
    yrow[2*tid+1] = __floats2half2_rn((v.z - mean)*rstd*wv.z + bv.z,
                                      (v.w - mean)*rstd*wv.w + bv.w);
}

// ---------------- row softmax: half logits -> half probs, half2 vectorized ------
__global__ void softmax_k() {
    int z = blockIdx.y;            // b*4 + head
    int b = z >> 2;
    int Nd = 1025 + g_M[b];
    int row = blockIdx.x;
    if (row >= Nd) return;
    __half2* sh2 = (__half2*)(g_Sh + (size_t)z*NPAD*SLD + (size_t)row*SLD);
    int tid = threadIdx.x;
    __shared__ float red[8];

    // 7 half2 per thread: 256*7*2 = 3584 >= SLD
    float2 vals[7];
    float m = -3.4e38f;
    #pragma unroll
    for (int t = 0; t < 7; t++) {
        int j2 = tid + t*256;
        int c0 = j2 << 1;
        if (c0 < Nd) {
            float2 v = __half22float2(sh2[j2]);
            vals[t] = v;
            m = fmaxf(m, v.x);
            if (c0 + 1 < Nd) m = fmaxf(m, v.y);
        }
    }
    m = warpMax(m);
    if ((tid & 31) == 0) red[tid>>5] = m;
    __syncthreads();
    if (tid == 0) {
        float v = red[0];
        #pragma unroll
        for (int i = 1; i < 8; i++) v = fmaxf(v, red[i]);
        red[0] = v;
    }
    __syncthreads();
    m = red[0];
    __syncthreads();

    float sum = 0.f;
    #pragma unroll
    for (int t = 0; t < 7; t++) {
        int j2 = tid + t*256;
        int c0 = j2 << 1;
        if (c0 < Nd) {
            float e0 = expf(vals[t].x - m);
            float e1 = (c0 + 1 < Nd) ? expf(vals[t].y - m) : 0.f;
            vals[t].x = e0; vals[t].y = e1;
            sum += e0 + e1;
        }
    }
    sum = warpSum(sum);
    if ((tid & 31) == 0) red[tid>>5] = sum;
    __syncthreads();
    if (tid == 0) {
        float v = 0.f;
        #pragma unroll
        for (int i = 0; i < 8; i++) v += red[i];
        red[0] = v;
    }
    __syncthreads();
    float inv = 1.0f / red[0];
    #pragma unroll
    for (int t = 0; t < 7; t++) {
        int j2 = tid + t*256;
        int c0 = j2 << 1;
        if (c0 + 1 < Nd) {
            sh2[j2] = __floats2half2_rn(vals[t].x * inv, vals[t].y * inv);
        } else if (c0 < Nd) {
            // odd tail: keep pad column exactly 0
            ((__half*)sh2)[c0] = __float2half_rn(vals[t].x * inv);
        }
    }
}

// ================= shared GEMM helpers ==========================================
__device__ __forceinline__ int dimval(int st, int dyn, int b) {
    if (dyn == 1) return 1025 + g_M[b];
    if (dyn == 2) return g_M[b];
    return st;
}
__device__ __forceinline__ void cpa16(uint32_t dst, const void* src, int srcBytes) {
    asm volatile("cp.async.cg.shared.global [%0], [%1], 16, %2;"
                 :: "r"(dst), "l"(src), "r"(srcBytes));
}
#define MMA_F16(d, a, bq)                                                \
    asm volatile("mma.sync.aligned.m16n8k16.row.col.f32.f16.f16.f32 "    \
        "{%0,%1,%2,%3},{%4,%5,%6,%7},{%8,%9},{%0,%1,%2,%3};"             \
        : "+f"(d[0]),"+f"(d[1]),"+f"(d[2]),"+f"(d[3])                    \
        : "r"(a[0]),"r"(a[1]),"r"(a[2]),"r"(a[3]),"r"(bq[0]),"r"(bq[1]))
#define LDSM4(r0, r1, r2, r3, addr)                                      \
    asm volatile("ldmatrix.sync.aligned.m8n8.x4.shared.b16 "             \
        "{%0,%1,%2,%3}, [%4];"                                           \
        : "=r"(r0), "=r"(r1), "=r"(r2), "=r"(r3) : "r"(addr))
#define LDSM2(r0, r1, addr)                                              \
    asm volatile("ldmatrix.sync.aligned.m8n8.x2.shared.b16 "             \
        "{%0,%1}, [%2];"                                                 \
        : "=r"(r0), "=r"(r1) : "r"(addr))

// =========================== fp16 tensor-core GEMM ==============================
// C = alpha * A @ B^T (+bias)(+gelu)(+=C fp32)(OUTH: half store)
// A: half [M][K] row-major; B: half [N][K] row-major.
// 128x128x32 CTA tile, 8 warps (2x4), 64x32 warp tile, m16n8k16 f16 mma,
// 2-stage cp.async double buffer, ldmatrix fragment loads.
template<int EPI, bool ACCUM, bool OUTH>
__global__ void __launch_bounds__(256, 2) gemm_h(
    const __half* __restrict__ A, long long aOut, long long aIn, int lda,
    const __half* __restrict__ B, long long bOut, long long bIn, int ldb,
    void* __restrict__ Cv, long long cOut, long long cIn, int ldc,
    const float* __restrict__ bias,
    int nInner, int Mst, int Nst, int Kst,
    int dynM, int dynN, int dynK, float alpha)
{
    int z = blockIdx.z;
    int b = z / nInner, ii = z - b*nInner;
    int Mr = dimval(Mst, dynM, b);
    int Nc = dimval(Nst, dynN, b);
    int K  = dimval(Kst, dynK, b);
    int Kpad = (K + 31) & ~31;
    int m0 = blockIdx.y * 128, n0 = blockIdx.x * 128;
    if (m0 >= Mr || n0 >= Nc) return;
    A += b*aOut + ii*aIn;
    B += b*bOut + ii*bIn;

    __shared__ __align__(16) uint32_t Asm[2*2560];
    __shared__ __align__(16) uint32_t Bsm[2*2560];
    uint32_t sA = (uint32_t)__cvta_generic_to_shared(Asm);
    uint32_t sB = (uint32_t)__cvta_generic_to_shared(Bsm);

    int tid  = threadIdx.x;
    int wid  = tid >> 5, lane = tid & 31;
    int wm   = (wid >> 2) * 64;
    int wn   = (wid & 3) * 32;
    int g    = lane >> 2, t4 = lane & 3;

    float acc[4][4][4];
    #pragma unroll
    for (int i = 0; i < 4; i++)
        #pragma unroll
        for (int j = 0; j < 4; j++)
            #pragma unroll
            for (int e = 0; e < 4; e++) acc[i][j][e] = 0.f;

    auto issue = [&](int kt, int buf) {
        int k0 = kt << 5;
        #pragma unroll
        for (int i = 0; i < 2; i++) {
            int idx = tid + 256*i;
            int r = idx >> 2, cw = (idx & 3) << 2;
            int gm = m0 + r;
            bool ok = gm < Mr;
            const __half* src = ok ? (A + (long long)gm*lda + k0 + (cw<<1)) : A;
            cpa16(sA + (uint32_t)(buf*2560 + r*20 + cw)*4, src, ok ? 16 : 0);
        }
        #pragma unroll
        for (int i = 0; i < 2; i++) {
            int idx = tid + 256*i;
            int r = idx >> 2, cw = (idx & 3) << 2;
            int gn = n0 + r;
            bool ok = gn < Nc;
            const __half* src = ok ? (B + (long long)gn*ldb + k0 + (cw<<1)) : B;
            cpa16(sB + (uint32_t)(buf*2560 + r*20 + cw)*4, src, ok ? 16 : 0);
        }
    };

    int lane16 = lane & 15;
    int laneh  = lane >> 4;
    int lane8  = lane & 7;
    int laneb  = (lane >> 3) & 1;

    auto compute = [&](int buf) {
        uint32_t aBase = sA + (uint32_t)(buf*2560 + (wm + lane16)*20 + laneh*4)*4;
        uint32_t bBase = sB + (uint32_t)(buf*2560 + (wn + lane8 )*20 + laneb*4)*4;
        #pragma unroll
        for (int ks = 0; ks < 2; ks++) {
            uint32_t kOff = (uint32_t)(ks*8)*4;
            uint32_t af[4][4], bf[4][2];
            #pragma unroll
            for (int mf = 0; mf < 4; mf++)
                LDSM4(af[mf][0], af[mf][1], af[mf][2], af[mf][3],
                      aBase + (uint32_t)(mf*16*20)*4 + kOff);
            #pragma unroll
            for (int nf = 0; nf < 4; nf++)
                LDSM2(bf[nf][0], bf[nf][1],
                      bBase + (uint32_t)(nf*8*20)*4 + kOff);
            #pragma unroll
            for (int mf = 0; mf < 4; mf++)
                #pragma unroll
                for (int nf = 0; nf < 4; nf++)
                    MMA_F16(acc[mf][nf], af[mf], bf[nf]);
        }
    };

    int ntiles = Kpad >> 5;
    issue(0, 0);
    asm volatile("cp.async.commit_group;" ::: "memory");
    for (int it = 0; it < ntiles; it++) {
        if (it + 1 < ntiles) issue(it + 1, (it + 1) & 1);
        asm volatile("cp.async.commit_group;" ::: "memory");
        asm volatile("cp.async.wait_group 1;" ::: "memory");
        __syncthreads();
        compute(it & 1);
        __syncthreads();
    }

    float*  Cf = (float*) Cv;
    __half* Ch = (__half*)Cv;
    long long cbase = b*cOut + ii*cIn;
    #pragma unroll
    for (int mf = 0; mf < 4; mf++) {
        #pragma unroll
        for (int nf = 0; nf < 4; nf++) {
            int gn0 = n0 + wn + nf*8 + 2*t4;
            #pragma unroll
            for (int rr = 0; rr < 2; rr++) {
                int gm = m0 + wm + mf*16 + g + rr*8;
                if (gm >= Mr) continue;
                float v0 = acc[mf][nf][2*rr    ] * alpha;
                float v1 = acc[mf][nf][2*rr + 1] * alpha;
                if (bias) { v0 += bias[gn0]; v1 += bias[gn0 + 1]; }
                if (EPI == 1) { v0 = geluf(v0); v1 = geluf(v1); }
                long long off = cbase + (long long)gm*ldc + gn0;
                if (OUTH) {
                    if (gn0 + 1 < Nc)
                        *(__half2*)(Ch + off) = __floats2half2_rn(v0, v1);
                    else if (gn0 < Nc)
                        Ch[off] = __float2half_rn(v0);
                } else {
                    if (gn0 < Nc)     { if (ACCUM) Cf[off]   += v0; else Cf[off]   = v0; }
                    if (gn0 + 1 < Nc) { if (ACCUM) Cf[off+1] += v1; else Cf[off+1] = v1; }
                }
            }
        }
    }
}

// ---------------- output (float4) ------------------------------------------------
__global__ void out_k(const float* __restrict__ img, float* __restrict__ out) {
    int b = blockIdx.y, t = blockIdx.x;
    const float4* src = (g_M[b] == 0)
        ? (const float4*)(img + ((size_t)b*1024 + t) * 1024)
        : (const float4*)(g_X + ((size_t)b*NPAD + t) * 1024);
    float4* o = (float4*)(out + ((size_t)b*1024 + t) * 1024);
    o[threadIdx.x] = src[threadIdx.x];
}

// ================================ host ==========================================
extern "C" void kernel_launch(void* const* d_in, const int* in_sizes, int n_in,
                              void* d_out, int out_size) {
    const float* img   = (const float*)d_in[0];
    const float* depth = (const float*)d_in[1];
    const int*   mask  = (const int*)  d_in[2];
    const float* gauss = (const float*)d_in[5];
    const float* w1    = (const float*)d_in[6];
    const float* b1    = (const float*)d_in[7];
    const float* w2    = (const float*)d_in[8];
    const float* b2    = (const float*)d_in[9];
    const float* sep   = (const float*)d_in[10];
    const float* ln1w  = (const float*)d_in[11];
    const float* ln1b  = (const float*)d_in[12];
    const float* qkvw  = (const float*)d_in[13];
    const float* qkvb  = (const float*)d_in[14];
    const float* projw = (const float*)d_in[15];
    const float* projb = (const float*)d_in[16];
    const float* ln2w  = (const float*)d_in[17];
    const float* ln2b  = (const float*)d_in[18];
    const float* m1w   = (const float*)d_in[19];
    const float* m1b   = (const float*)d_in[20];
    const float* m2w   = (const float*)d_in[21];
    const float* m2b   = (const float*)d_in[22];
    float* out = (float*)d_out;

    float *pX, *pPft;
    __half *pYh, *pQKVh, *pSh, *pHh, *pVt, *pHph, *pWch;
    cudaGetSymbolAddress((void**)&pX,    g_X);
    cudaGetSymbolAddress((void**)&pPft,  g_Pft);
    cudaGetSymbolAddress((void**)&pYh,   g_Yh);
    cudaGetSymbolAddress((void**)&pQKVh, g_QKVh);
    cudaGetSymbolAddress((void**)&pSh,   g_Sh);
    cudaGetSymbolAddress((void**)&pHh,   g_Hh);
    cudaGetSymbolAddress((void**)&pVt,   g_Vt);
    cudaGetSymbolAddress((void**)&pHph,  g_Hph);
    cudaGetSymbolAddress((void**)&pWch,  g_Wch);

    const long long SX   = (long long)NPAD * 1024;
    const long long SQKV = (long long)NPAD * 3072;
    const long long SH   = (long long)NPAD * 4096;
    const long long SS1  = (long long)NPAD * SLD;    // per head
    const long long SSB  = 4LL * SS1;                // per batch

    // --- transpose+round all GEMM weights to half [N][K] once per call ---
    {
        dim3 blk(32, 8);
        wtr_k<<<dim3(96, 32, 2),  blk>>>(qkvw,  pWch + WOFF_QKV,  1024, 3072);
        wtr_k<<<dim3(32, 32, 2),  blk>>>(projw, pWch + WOFF_PROJ, 1024, 1024);
        wtr_k<<<dim3(128, 32, 2), blk>>>(m1w,   pWch + WOFF_M1,   1024, 4096);
        wtr_k<<<dim3(32, 128, 2), blk>>>(m2w,   pWch + WOFF_M2,   4096, 1024);
        wtr_k<<<dim3(32, 16, 1),  blk>>>(w2,    pWch + WOFF_W2,    512, 1024);
    }
    const __half* qkvT  = pWch + WOFF_QKV;
    const __half* projT = pWch + WOFF_PROJ;
    const __half* m1T   = pWch + WOFF_M1;
    const __half* m2T   = pWch + WOFF_M2;
    const __half* w2T   = pWch + WOFF_W2;

    compact_k<<<NBATCH, 256>>>(mask);
    qpe_k<<<1024, 256>>>(gauss);
    pembed_k<<<dim3(GPTS, NBATCH), 256>>>(depth, gauss, w1, b1);

    // prompt features: Pft = Hp @ w2 + b2 (rows = g_M[b]) -> fp32 (feeds X)
    gemm_h<0,false,false><<<dim3(8, 18, NBATCH), 256>>>(
        pHph, (long long)GPTS*512, 0, 512,
        w2T, 0, 0, 512,
        pPft, (long long)GPTS*1024, 0, 1024,
        b2, 1, 0, 1024, 512, 2, 0, 0, 1.0f);

    build_x<<<dim3(NMAXT, NBATCH), 256>>>(img, sep);

    for (int i = 0; i < 2; i++) {
        if (i) sep_rep<<<NBATCH, 256>>>(sep + (size_t)i*1024);

        ln_k<<<dim3(NMAXT, NBATCH), 256>>>(pX, pYh, ln1w + i*1024, ln1b + i*1024);

        // QKV = Y @ qkv_w + qkv_b  -> half
        gemm_h<0,false,true><<<dim3(24, 27, NBATCH), 256>>>(
            pYh, SX, 0, 1024,
            qkvT + (size_t)i*3072*1024, 0, 0, 1024,
            pQKVh, SQKV, 0, 3072,
            qkvb + (size_t)i*3072, 1, 0, 3072, 1024, 1, 0, 0, 1.0f);

        // V transpose for S@V B-operand
        vtr_k<<<dim3(105, 32, NBATCH), dim3(32, 8)>>>(pQKVh, pVt);

        // S = Q K^T / 16 -> half logits directly (per head, z = b*4+h)
        gemm_h<0,false,true><<<dim3(27, 27, NBATCH*4), 256>>>(
            pQKVh, SQKV, 256, 3072,
            pQKVh + 1024, SQKV, 256, 3072,
            pSh, SSB, SS1, SLD,
            nullptr, 4, 0, 0, 256, 1, 1, 0, 0.0625f);

        softmax_k<<<dim3(NMAXT, NBATCH*4), 256>>>();

        // O = Sh @ Vt^T -> Yh half (per-head column slice)
        gemm_h<0,false,true><<<dim3(2, 27, NBATCH*4), 256>>>(
            pSh, SSB, SS1, SLD,
            pVt, (long long)1024*NPAD, (long long)256*NPAD, NPAD,
            pYh, SX, 256, 1024,
            nullptr, 4, 0, 256, 0, 1, 0, 1, 1.0f);

        // X += O @ proj_w + proj_b  (residual fp32)
        gemm_h<0,true,false><<<dim3(8, 27, NBATCH), 256>>>(
            pYh, SX, 0, 1024,
            projT + (size_t)i*1024*1024, 0, 0, 1024,
            pX, SX, 0, 1024,
            projb + (size_t)i*1024, 1, 0, 1024, 1024, 1, 0, 0, 1.0f);

        ln_k<<<dim3(NMAXT, NBATCH), 256>>>(pX, pYh, ln2w + i*1024, ln2b + i*1024);

        // H = gelu(Y @ mlp_w1 + mlp_b1) -> half
        gemm_h<1,false,true><<<dim3(32, 27, NBATCH), 256>>>(
            pYh, SX, 0, 1024,
            m1T + (size_t)i*4096*1024, 0, 0, 1024,
            pHh, SH, 0, 4096,
            m1b + (size_t)i*4096, 1, 0, 4096, 1024, 1, 0, 0, 1.0f);

        // X += H @ mlp_w2 + mlp_b2  (residual fp32)
        gemm_h<0,true,false><<<dim3(8, 27, NBATCH), 256>>>(
            pHh, SH, 0, 4096,
            m2T + (size_t)i*1024*4096, 0, 0, 4096,
            pX, SX, 0, 1024,
            m2b + (size_t)i*1024, 1, 0, 1024, 4096, 1, 0, 0, 1.0f);
    }

    out_k<<<dim3(1024, NBATCH), 256>>>(img, out);
}

// round 16
// speedup vs baseline: 1.0566x; 1.0018x over previous
#include <cuda_runtime.h>
#include <cuda_fp16.h>
#include <math.h>
#include <stdint.h>

#define NMAXT 3329      // 1024 query + 1 sep + 2304 max prompts (logical)
#define NPAD  3344      // token-dim padding
#define SLD   3344      // score-matrix row stride
#define GPTS  2304
#define NBATCH 4

// transposed-half-weight scratch layout (element offsets)
#define WOFF_QKV  0LL                    // 2 x [3072][1024]
#define WOFF_PROJ 6291456LL              // 2 x [1024][1024]
#define WOFF_M1   8388608LL              // 2 x [4096][1024]
#define WOFF_M2   16777216LL             // 2 x [1024][4096]
#define WOFF_W2   25165824LL             // [1024][512]
#define WC_TOTAL  25690112LL

// ---------------- static device scratch (zero-initialized, never freed) ---------
__device__ int    g_M[NBATCH];
__device__ int    g_rows[NBATCH*GPTS];
__device__ int    g_cols[NBATCH*GPTS];
__device__ float  g_X   [(size_t)NBATCH*NPAD*1024];            // residual, fp32
__device__ __half g_Yh  [(size_t)NBATCH*NPAD*1024];            // LN out / attn out
__device__ __half g_QKVh[(size_t)NBATCH*NPAD*3072];            // pad rows stay 0
__device__ __half g_Sh  [(size_t)NBATCH*4*NPAD*SLD];           // logits->probs, pad 0
__device__ __half g_Hh  [(size_t)NBATCH*NPAD*4096];            // MLP hidden
__device__ __half g_Vt  [(size_t)NBATCH*1024*NPAD];            // V transposed [dim][tok]
__device__ float  g_Qpe [1024*1024];
__device__ float  g_Ppe [(size_t)NBATCH*GPTS*1024];
__device__ __half g_Hph [(size_t)NBATCH*GPTS*512];
__device__ float  g_Pft [(size_t)NBATCH*GPTS*1024];
__device__ __half g_Wch [WC_TOTAL];

__device__ __forceinline__ float geluf(float x) {
    return 0.5f * x * (1.0f + erff(x * 0.7071067811865475f));
}
__device__ __forceinline__ float warpSum(float v) {
    #pragma unroll
    for (int o = 16; o; o >>= 1) v += __shfl_xor_sync(0xFFFFFFFFu, v, o);
    return v;
}
__device__ __forceinline__ float warpMax(float v) {
    #pragma unroll
    for (int o = 16; o; o >>= 1) v = fmaxf(v, __shfl_xor_sync(0xFFFFFFFFu, v, o));
    return v;
}

// ---------------- weight transpose fp32[K][N] -> half[N][K] ---------------------
__global__ void wtr_k(const float* __restrict__ src, __half* __restrict__ dst,
                      int K, int N) {
    __shared__ float t[32][33];
    src += (size_t)blockIdx.z * K * N;
    dst += (size_t)blockIdx.z * K * N;
    int n0 = blockIdx.x * 32, k0 = blockIdx.y * 32;
    int tx = threadIdx.x, ty = threadIdx.y;
    #pragma unroll
    for (int i = 0; i < 32; i += 8)
        t[ty + i][tx] = src[(size_t)(k0 + ty + i) * N + n0 + tx];
    __syncthreads();
    #pragma unroll
    for (int i = 0; i < 32; i += 8)
        dst[(size_t)(n0 + ty + i) * K + k0 + tx] = __float2half_rn(t[tx][ty + i]);
}

// ---------------- V transpose half [tok][dim] -> half [dim][tok] ----------------
__global__ void vtr_k(const __half* __restrict__ QKVh, __half* __restrict__ Vt) {
    __shared__ __half t[32][40];
    int b = blockIdx.z;
    const __half* src = QKVh + (size_t)b*NPAD*3072 + 2048;
    __half* dst = Vt + (size_t)b*1024*NPAD;
    int t0 = blockIdx.x * 32, n0 = blockIdx.y * 32;
    int tx = threadIdx.x, ty = threadIdx.y;
    #pragma unroll
    for (int i = 0; i < 32; i += 8) {
        int tt = t0 + ty + i;
        t[ty + i][tx] = (tt < NPAD) ? src[(size_t)tt*3072 + n0 + tx] : __half(0.f);
    }
    __syncthreads();
    #pragma unroll
    for (int i = 0; i < 32; i += 8) {
        int tt = t0 + tx;
        if (tt < NPAD) dst[(size_t)(n0 + ty + i)*NPAD + tt] = t[tx][ty + i];
    }
}

// ------- mask compaction: parallel block scan, order == np.nonzero --------------
__global__ void compact_k(const int* __restrict__ mask) {
    int b = blockIdx.x;
    const int* mb = mask + b * GPTS;
    int tid = threadIdx.x, lane = tid & 31, w = tid >> 5;
    __shared__ int warpTot[8], warpBase[8];

    int flags[9];
    int cnt = 0;
    int base0 = tid * 9;
    #pragma unroll
    for (int j = 0; j < 9; j++) {
        flags[j] = (mb[base0 + j] > 0) ? 1 : 0;
        cnt += flags[j];
    }
    int ws = cnt;
    #pragma unroll
    for (int o = 1; o < 32; o <<= 1) {
        int v = __shfl_up_sync(0xFFFFFFFFu, ws, o);
        if (lane >= o) ws += v;
    }
    if (lane == 31) warpTot[w] = ws;
    __syncthreads();
    if (tid == 0) {
        int acc = 0;
        #pragma unroll
        for (int i = 0; i < 8; i++) { warpBase[i] = acc; acc += warpTot[i]; }
        g_M[b] = acc;
    }
    __syncthreads();
    int pos = warpBase[w] + ws - cnt;
    #pragma unroll
    for (int j = 0; j < 9; j++) {
        if (flags[j]) {
            int idx = base0 + j;
            g_rows[b*GPTS + pos] = idx / 48;
            g_cols[b*GPTS + pos] = idx % 48;
            pos++;
        }
    }
}

// ---------------- query positional encoding -------------------------------------
__global__ void qpe_k(const float* __restrict__ gauss) {
    int t = blockIdx.x;            // t = i*32 + j
    int i = t >> 5, j = t & 31;
    float cx = 2.0f * ((j + 0.5f) / 32.0f) - 1.0f;
    float cy = 2.0f * ((i + 0.5f) / 32.0f) - 1.0f;
    for (int k = threadIdx.x; k < 512; k += 256) {
        float ang = 6.283185307179586f * (cx * gauss[k] + cy * gauss[512 + k]);
        g_Qpe[(size_t)t*1024 + k]       = sinf(ang);
        g_Qpe[(size_t)t*1024 + 512 + k] = cosf(ang);
    }
}

// ------------- prompt PE + depth hidden layer gelu(d*w1+b1) ---------------------
__global__ void pembed_k(const float* __restrict__ depth, const float* __restrict__ gauss,
                         const float* __restrict__ w1, const float* __restrict__ b1) {
    int b = blockIdx.y, j = blockIdx.x;
    if (j >= g_M[b]) return;
    int r = g_rows[b*GPTS + j], c = g_cols[b*GPTS + j];
    float cx = 2.0f * ((c + 0.5f) / 48.0f) - 1.0f;
    float cy = 2.0f * ((r + 0.5f) / 48.0f) - 1.0f;
    float d = depth[b*GPTS + r*48 + c];
    size_t base = (size_t)b*GPTS + j;
    for (int k = threadIdx.x; k < 512; k += 256) {
        float ang = 6.283185307179586f * (cx * gauss[k] + cy * gauss[512 + k]);
        g_Ppe[base*1024 + k]       = sinf(ang);
        g_Ppe[base*1024 + 512 + k] = cosf(ang);
        g_Hph[base*512  + k]       = __float2half_rn(geluf(fmaf(d, w1[k], b1[k])));
    }
}

// ---------------- build residual stream (float4) --------------------------------
__global__ void build_x(const float* __restrict__ img, const float* __restrict__ sep0) {
    int b = blockIdx.y, t = blockIdx.x;
    if (t >= 1025 + g_M[b]) return;
    int c = threadIdx.x;
    float4* x4 = (float4*)(g_X + ((size_t)b*NPAD + t) * 1024);
    if (t < 1024) {
        float4 a = ((const float4*)(img + ((size_t)b*1024 + t) * 1024))[c];
        float4 p = ((const float4*)(g_Qpe + (size_t)t*1024))[c];
        a.x += p.x; a.y += p.y; a.z += p.z; a.w += p.w;
        x4[c] = a;
    } else if (t == 1024) {
        x4[c] = ((const float4*)sep0)[c];
    } else {
        size_t base = (size_t)b*GPTS + (t - 1025);
        float4 a = ((const float4*)(g_Pft + base*1024))[c];
        float4 p = ((const float4*)(g_Ppe + base*1024))[c];
        a.x += p.x; a.y += p.y; a.z += p.z; a.w += p.w;
        x4[c] = a;
    }
}

__global__ void sep_rep(const float* __restrict__ sep1) {
    int b = blockIdx.x;
    float4* x4 = (float4*)(g_X + ((size_t)b*NPAD + 1024) * 1024);
    x4[threadIdx.x] = ((const float4*)sep1)[threadIdx.x];
}

// ---------------- layernorm: fp32 in -> half out --------------------------------
__global__ void ln_k(const float* __restrict__ Xin, __half* __restrict__ Yout,
                     const float* __restrict__ w, const float* __restrict__ bb) {
    int b = blockIdx.y, t = blockIdx.x;
    if (t >= 1025 + g_M[b]) return;
    int tid = threadIdx.x;
    const float4* x4 = (const float4*)(Xin + ((size_t)b*NPAD + t) * 1024);
    float4 v = x4[tid];
    float s  = v.x + v.y + v.z + v.w;
    float sq = v.x*v.x + v.y*v.y + v.z*v.z + v.w*v.w;
    __shared__ float shs[8], shq[8], res[2];
    float ws = warpSum(s), wq = warpSum(sq);
    if ((tid & 31) == 0) { shs[tid>>5] = ws; shq[tid>>5] = wq; }
    __syncthreads();
    if (tid == 0) {
        float a = 0.f, q = 0.f;
        #pragma unroll
        for (int i = 0; i < 8; i++) { a += shs[i]; q += shq[i]; }
        res[0] = a; res[1] = q;
    }
    __syncthreads();
    float mean = res[0] * (1.0f/1024.0f);
    float var  = res[1] * (1.0f/1024.0f) - mean*mean;
    float rstd = rsqrtf(var + 1e-5f);
    float4 wv = ((const float4*)w)[tid];
    float4 bv = ((const float4*)bb)[tid];
    __half2* yrow = (__half2*)(Yout + ((size_t)b*NPAD + t) * 1024);
    yrow[2*tid]   = __floats2half2_rn((v.x - mean)*rstd*wv.x + bv.x,
                                      (v.y - mean)*rstd*wv.y + bv.y);
    yrow[2*tid+1] = __floats2half2_rn((v.z - mean)*rstd*wv.z + bv.z,
                                      (v.w - mean)*rstd*wv.w + bv.w);
}

// ---------------- row softmax: half logits -> half probs, half2 vectorized ------
__global__ void softmax_k() {
    int z = blockIdx.y;            // b*4 + head
    int b = z >> 2;
    int Nd = 1025 + g_M[b];
    int row = blockIdx.x;
    if (row >= Nd) return;
    __half2* sh2 = (__half2*)(g_Sh + (size_t)z*NPAD*SLD + (size_t)row*SLD);
    int tid = threadIdx.x;
    __shared__ float red[8];

    float2 vals[7];
    float m = -3.4e38f;
    #pragma unroll
    for (int t = 0; t < 7; t++) {
        int j2 = tid + t*256;
        int c0 = j2 << 1;
        if (c0 < Nd) {
            float2 v = __half22float2(sh2[j2]);
            vals[t] = v;
            m = fmaxf(m, v.x);
            if (c0 + 1 < Nd) m = fmaxf(m, v.y);
        }
    }
    m = warpMax(m);
    if ((tid & 31) == 0) red[tid>>5] = m;
    __syncthreads();
    if (tid == 0) {
        float v = red[0];
        #pragma unroll
        for (int i = 1; i < 8; i++) v = fmaxf(v, red[i]);
        red[0] = v;
    }
    __syncthreads();
    m = red[0];
    __syncthreads();

    float sum = 0.f;
    #pragma unroll
    for (int t = 0; t < 7; t++) {
        int j2 = tid + t*256;
        int c0 = j2 << 1;
        if (c0 < Nd) {
            float e0 = expf(vals[t].x - m);
            float e1 = (c0 + 1 < Nd) ? expf(vals[t].y - m) : 0.f;
            vals[t].x = e0; vals[t].y = e1;
            sum += e0 + e1;
        }
    }
    sum = warpSum(sum);
    if ((tid & 31) == 0) red[tid>>5] = sum;
    __syncthreads();
    if (tid == 0) {
        float v = 0.f;
        #pragma unroll
        for (int i = 0; i < 8; i++) v += red[i];
        red[0] = v;
    }
    __syncthreads();
    float inv = 1.0f / red[0];
    #pragma unroll
    for (int t = 0; t < 7; t++) {
        int j2 = tid + t*256;
        int c0 = j2 << 1;
        if (c0 + 1 < Nd) {
            sh2[j2] = __floats2half2_rn(vals[t].x * inv, vals[t].y * inv);
        } else if (c0 < Nd) {
            ((__half*)sh2)[c0] = __float2half_rn(vals[t].x * inv);
        }
    }
}

// ================= shared GEMM helpers ==========================================
__device__ __forceinline__ int dimval(int st, int dyn, int b) {
    if (dyn == 1) return 1025 + g_M[b];
    if (dyn == 2) return g_M[b];
    return st;
}
__device__ __forceinline__ void cpa16(uint32_t dst, const void* src, int srcBytes) {
    asm volatile("cp.async.cg.shared.global [%0], [%1], 16, %2;"
                 :: "r"(dst), "l"(src), "r"(srcBytes));
}
#define MMA_F16(d, a, bq)                                                \
    asm volatile("mma.sync.aligned.m16n8k16.row.col.f32.f16.f16.f32 "    \
        "{%0,%1,%2,%3},{%4,%5,%6,%7},{%8,%9},{%0,%1,%2,%3};"             \
        : "+f"(d[0]),"+f"(d[1]),"+f"(d[2]),"+f"(d[3])                    \
        : "r"(a[0]),"r"(a[1]),"r"(a[2]),"r"(a[3]),"r"(bq[0]),"r"(bq[1]))
#define MMA_F16H(d, a, bq)                                               \
    asm volatile("mma.sync.aligned.m16n8k16.row.col.f16.f16.f16.f16 "    \
        "{%0,%1},{%2,%3,%4,%5},{%6,%7},{%0,%1};"                         \
        : "+r"(d[0]),"+r"(d[1])                                          \
        : "r"(a[0]),"r"(a[1]),"r"(a[2]),"r"(a[3]),"r"(bq[0]),"r"(bq[1]))
#define LDSM4(r0, r1, r2, r3, addr)                                      \
    asm volatile("ldmatrix.sync.aligned.m8n8.x4.shared.b16 "             \
        "{%0,%1,%2,%3}, [%4];"                                           \
        : "=r"(r0), "=r"(r1), "=r"(r2), "=r"(r3) : "r"(addr))
#define LDSM2(r0, r1, addr)                                              \
    asm volatile("ldmatrix.sync.aligned.m8n8.x2.shared.b16 "             \
        "{%0,%1}, [%2];"                                                 \
        : "=r"(r0), "=r"(r1) : "r"(addr))

// =========================== fp16 tensor-core GEMM (f32 acc) ====================
template<int EPI, bool ACCUM, bool OUTH>
__global__ void __launch_bounds__(256, 2) gemm_h(
    const __half* __restrict__ A, long long aOut, long long aIn, int lda,
    const __half* __restrict__ B, long long bOut, long long bIn, int ldb,
    void* __restrict__ Cv, long long cOut, long long cIn, int ldc,
    const float* __restrict__ bias,
    int nInner, int Mst, int Nst, int Kst,
    int dynM, int dynN, int dynK, float alpha)
{
    int z = blockIdx.z;
    int b = z / nInner, ii = z - b*nInner;
    int Mr = dimval(Mst, dynM, b);
    int Nc = dimval(Nst, dynN, b);
    int K  = dimval(Kst, dynK, b);
    int Kpad = (K + 31) & ~31;
    int m0 = blockIdx.y * 128, n0 = blockIdx.x * 128;
    if (m0 >= Mr || n0 >= Nc) return;
    A += b*aOut + ii*aIn;
    B += b*bOut + ii*bIn;

    __shared__ __align__(16) uint32_t Asm[2*2560];
    __shared__ __align__(16) uint32_t Bsm[2*2560];
    uint32_t sA = (uint32_t)__cvta_generic_to_shared(Asm);
    uint32_t sB = (uint32_t)__cvta_generic_to_shared(Bsm);

    int tid  = threadIdx.x;
    int wid  = tid >> 5, lane = tid & 31;
    int wm   = (wid >> 2) * 64;
    int wn   = (wid & 3) * 32;
    int g    = lane >> 2, t4 = lane & 3;

    float acc[4][4][4];
    #pragma unroll
    for (int i = 0; i < 4; i++)
        #pragma unroll
        for (int j = 0; j < 4; j++)
            #pragma unroll
            for (int e = 0; e < 4; e++) acc[i][j][e] = 0.f;

    auto issue = [&](int kt, int buf) {
        int k0 = kt << 5;
        #pragma unroll
        for (int i = 0; i < 2; i++) {
            int idx = tid + 256*i;
            int r = idx >> 2, cw = (idx & 3) << 2;
            int gm = m0 + r;
            bool ok = gm < Mr;
            const __half* src = ok ? (A + (long long)gm*lda + k0 + (cw<<1)) : A;
            cpa16(sA + (uint32_t)(buf*2560 + r*20 + cw)*4, src, ok ? 16 : 0);
        }
        #pragma unroll
        for (int i = 0; i < 2; i++) {
            int idx = tid + 256*i;
            int r = idx >> 2, cw = (idx & 3) << 2;
            int gn = n0 + r;
            bool ok = gn < Nc;
            const __half* src = ok ? (B + (long long)gn*ldb + k0 + (cw<<1)) : B;
            cpa16(sB + (uint32_t)(buf*2560 + r*20 + cw)*4, src, ok ? 16 : 0);
        }
    };

    int lane16 = lane & 15;
    int laneh  = lane >> 4;
    int lane8  = lane & 7;
    int laneb  = (lane >> 3) & 1;

    auto compute = [&](int buf) {
        uint32_t aBase = sA + (uint32_t)(buf*2560 + (wm + lane16)*20 + laneh*4)*4;
        uint32_t bBase = sB + (uint32_t)(buf*2560 + (wn + lane8 )*20 + laneb*4)*4;
        #pragma unroll
        for (int ks = 0; ks < 2; ks++) {
            uint32_t kOff = (uint32_t)(ks*8)*4;
            uint32_t af[4][4], bf[4][2];
            #pragma unroll
            for (int mf = 0; mf < 4; mf++)
                LDSM4(af[mf][0], af[mf][1], af[mf][2], af[mf][3],
                      aBase + (uint32_t)(mf*16*20)*4 + kOff);
            #pragma unroll
            for (int nf = 0; nf < 4; nf++)
                LDSM2(bf[nf][0], bf[nf][1],
                      bBase + (uint32_t)(nf*8*20)*4 + kOff);
            #pragma unroll
            for (int mf = 0; mf < 4; mf++)
                #pragma unroll
                for (int nf = 0; nf < 4; nf++)
                    MMA_F16(acc[mf][nf], af[mf], bf[nf]);
        }
    };

    int ntiles = Kpad >> 5;
    issue(0, 0);
    asm volatile("cp.async.commit_group;" ::: "memory");
    for (int it = 0; it < ntiles; it++) {
        if (it + 1 < ntiles) issue(it + 1, (it + 1) & 1);
        asm volatile("cp.async.commit_group;" ::: "memory");
        asm volatile("cp.async.wait_group 1;" ::: "memory");
        __syncthreads();
        compute(it & 1);
        __syncthreads();
    }

    float*  Cf = (float*) Cv;
    __half* Ch = (__half*)Cv;
    long long cbase = b*cOut + ii*cIn;
    #pragma unroll
    for (int mf = 0; mf < 4; mf++) {
        #pragma unroll
        for (int nf = 0; nf < 4; nf++) {
            int gn0 = n0 + wn + nf*8 + 2*t4;
            #pragma unroll
            for (int rr = 0; rr < 2; rr++) {
                int gm = m0 + wm + mf*16 + g + rr*8;
                if (gm >= Mr) continue;
                float v0 = acc[mf][nf][2*rr    ] * alpha;
                float v1 = acc[mf][nf][2*rr + 1] * alpha;
                if (bias) { v0 += bias[gn0]; v1 += bias[gn0 + 1]; }
                if (EPI == 1) { v0 = geluf(v0); v1 = geluf(v1); }
                long long off = cbase + (long long)gm*ldc + gn0;
                if (OUTH) {
                    if (gn0 + 1 < Nc)
                        *(__half2*)(Ch + off) = __floats2half2_rn(v0, v1);
                    else if (gn0 < Nc)
                        Ch[off] = __float2half_rn(v0);
                } else {
                    if (gn0 < Nc)     { if (ACCUM) Cf[off]   += v0; else Cf[off]   = v0; }
                    if (gn0 + 1 < Nc) { if (ACCUM) Cf[off+1] += v1; else Cf[off+1] = v1; }
                }
            }
        }
    }
}

// ================== fp16 tensor-core GEMM, f16 accumulation (QK only) ===========
// C(half) = alpha * A @ B^T ; half accumulators (2x mma rate), half store.
__global__ void __launch_bounds__(256, 2) gemm_hh(
    const __half* __restrict__ A, long long aOut, long long aIn, int lda,
    const __half* __restrict__ B, long long bOut, long long bIn, int ldb,
    __half* __restrict__ C, long long cOut, long long cIn, int ldc,
    int nInner, float alpha)
{
    int z = blockIdx.z;
    int b = z / nInner, ii = z - b*nInner;
    int Mr = 1025 + g_M[b];
    int Nc = Mr;
    int K  = 256;
    int m0 = blockIdx.y * 128, n0 = blockIdx.x * 128;
    if (m0 >= Mr || n0 >= Nc) return;
    A += b*aOut + ii*aIn;
    B += b*bOut + ii*bIn;

    __shared__ __align__(16) uint32_t Asm[2*2560];
    __shared__ __align__(16) uint32_t Bsm[2*2560];
    uint32_t sA = (uint32_t)__cvta_generic_to_shared(Asm);
    uint32_t sB = (uint32_t)__cvta_generic_to_shared(Bsm);

    int tid  = threadIdx.x;
    int wid  = tid >> 5, lane = tid & 31;
    int wm   = (wid >> 2) * 64;
    int wn   = (wid & 3) * 32;
    int g    = lane >> 2, t4 = lane & 3;

    uint32_t acc[4][4][2];          // half2 accumulators
    #pragma unroll
    for (int i = 0; i < 4; i++)
        #pragma unroll
        for (int j = 0; j < 4; j++) { acc[i][j][0] = 0u; acc[i][j][1] = 0u; }

    auto issue = [&](int kt, int buf) {
        int k0 = kt << 5;
        #pragma unroll
        for (int i = 0; i < 2; i++) {
            int idx = tid + 256*i;
            int r = idx >> 2, cw = (idx & 3) << 2;
            int gm = m0 + r;
            bool ok = gm < Mr;
            const __half* src = ok ? (A + (long long)gm*lda + k0 + (cw<<1)) : A;
            cpa16(sA + (uint32_t)(buf*2560 + r*20 + cw)*4, src, ok ? 16 : 0);
        }
        #pragma unroll
        for (int i = 0; i < 2; i++) {
            int idx = tid + 256*i;
            int r = idx >> 2, cw = (idx & 3) << 2;
            int gn = n0 + r;
            bool ok = gn < Nc;
            const __half* src = ok ? (B + (long long)gn*ldb + k0 + (cw<<1)) : B;
            cpa16(sB + (uint32_t)(buf*2560 + r*20 + cw)*4, src, ok ? 16 : 0);
        }
    };

    int lane16 = lane & 15;
    int laneh  = lane >> 4;
    int lane8  = lane & 7;
    int laneb  = (lane >> 3) & 1;

    auto compute = [&](int buf) {
        uint32_t aBase = sA + (uint32_t)(buf*2560 + (wm + lane16)*20 + laneh*4)*4;
        uint32_t bBase = sB + (uint32_t)(buf*2560 + (wn + lane8 )*20 + laneb*4)*4;
        #pragma unroll
        for (int ks = 0; ks < 2; ks++) {
            uint32_t kOff = (uint32_t)(ks*8)*4;
            uint32_t af[4][4], bf[4][2];
            #pragma unroll
            for (int mf = 0; mf < 4; mf++)
                LDSM4(af[mf][0], af[mf][1], af[mf][2], af[mf][3],
                      aBase + (uint32_t)(mf*16*20)*4 + kOff);
            #pragma unroll
            for (int nf = 0; nf < 4; nf++)
                LDSM2(bf[nf][0], bf[nf][1],
                      bBase + (uint32_t)(nf*8*20)*4 + kOff);
            #pragma unroll
            for (int mf = 0; mf < 4; mf++)
                #pragma unroll
                for (int nf = 0; nf < 4; nf++)
                    MMA_F16H(acc[mf][nf], af[mf], bf[nf]);
        }
    };

    int ntiles = 8;                 // K=256 fixed
    issue(0, 0);
    asm volatile("cp.async.commit_group;" ::: "memory");
    for (int it = 0; it < ntiles; it++) {
        if (it + 1 < ntiles) issue(it + 1, (it + 1) & 1);
        asm volatile("cp.async.commit_group;" ::: "memory");
        asm volatile("cp.async.wait_group 1;" ::: "memory");
        __syncthreads();
        compute(it & 1);
        __syncthreads();
    }

    long long cbase = b*cOut + ii*cIn;
    #pragma unroll
    for (int mf = 0; mf < 4; mf++) {
        #pragma unroll
        for (int nf = 0; nf < 4; nf++) {
            int gn0 = n0 + wn + nf*8 + 2*t4;
            #pragma unroll
            for (int rr = 0; rr < 2; rr++) {
                int gm = m0 + wm + mf*16 + g + rr*8;
                if (gm >= Mr) continue;
                float2 vv = __half22float2(*(__half2*)&acc[mf][nf][rr]);
                float v0 = vv.x * alpha;
                float v1 = vv.y * alpha;
                long long off = cbase + (long long)gm*ldc + gn0;
                if (gn0 + 1 < Nc)
                    *(__half2*)(C + off) = __floats2half2_rn(v0, v1);
                else if (gn0 < Nc)
                    C[off] = __float2half_rn(v0);
            }
        }
    }
}

// ---------------- output (float4) ------------------------------------------------
__global__ void out_k(const float* __restrict__ img, float* __restrict__ out) {
    int b = blockIdx.y, t = blockIdx.x;
    const float4* src = (g_M[b] == 0)
        ? (const float4*)(img + ((size_t)b*1024 + t) * 1024)
        : (const float4*)(g_X + ((size_t)b*NPAD + t) * 1024);
    float4* o = (float4*)(out + ((size_t)b*1024 + t) * 1024);
    o[threadIdx.x] = src[threadIdx.x];
}

// ================================ host ==========================================
extern "C" void kernel_launch(void* const* d_in, const int* in_sizes, int n_in,
                              void* d_out, int out_size) {
    const float* img   = (const float*)d_in[0];
    const float* depth = (const float*)d_in[1];
    const int*   mask  = (const int*)  d_in[2];
    const float* gauss = (const float*)d_in[5];
    const float* w1    = (const float*)d_in[6];
    const float* b1    = (const float*)d_in[7];
    const float* w2    = (const float*)d_in[8];
    const float* b2    = (const float*)d_in[9];
    const float* sep   = (const float*)d_in[10];
    const float* ln1w  = (const float*)d_in[11];
    const float* ln1b  = (const float*)d_in[12];
    const float* qkvw  = (const float*)d_in[13];
    const float* qkvb  = (const float*)d_in[14];
    const float* projw = (const float*)d_in[15];
    const float* projb = (const float*)d_in[16];
    const float* ln2w  = (const float*)d_in[17];
    const float* ln2b  = (const float*)d_in[18];
    const float* m1w   = (const float*)d_in[19];
    const float* m1b   = (const float*)d_in[20];
    const float* m2w   = (const float*)d_in[21];
    const float* m2b   = (const float*)d_in[22];
    float* out = (float*)d_out;

    float *pX, *pPft;
    __half *pYh, *pQKVh, *pSh, *pHh, *pVt, *pHph, *pWch;
    cudaGetSymbolAddress((void**)&pX,    g_X);
    cudaGetSymbolAddress((void**)&pPft,  g_Pft);
    cudaGetSymbolAddress((void**)&pYh,   g_Yh);
    cudaGetSymbolAddress((void**)&pQKVh, g_QKVh);
    cudaGetSymbolAddress((void**)&pSh,   g_Sh);
    cudaGetSymbolAddress((void**)&pHh,   g_Hh);
    cudaGetSymbolAddress((void**)&pVt,   g_Vt);
    cudaGetSymbolAddress((void**)&pHph,  g_Hph);
    cudaGetSymbolAddress((void**)&pWch,  g_Wch);

    const long long SX   = (long long)NPAD * 1024;
    const long long SQKV = (long long)NPAD * 3072;
    const long long SH   = (long long)NPAD * 4096;
    const long long SS1  = (long long)NPAD * SLD;    // per head
    const long long SSB  = 4LL * SS1;                // per batch

    // --- transpose+round all GEMM weights to half [N][K] once per call ---
    {
        dim3 blk(32, 8);
        wtr_k<<<dim3(96, 32, 2),  blk>>>(qkvw,  pWch + WOFF_QKV,  1024, 3072);
        wtr_k<<<dim3(32, 32, 2),  blk>>>(projw, pWch + WOFF_PROJ, 1024, 1024);
        wtr_k<<<dim3(128, 32, 2), blk>>>(m1w,   pWch + WOFF_M1,   1024, 4096);
        wtr_k<<<dim3(32, 128, 2), blk>>>(m2w,   pWch + WOFF_M2,   4096, 1024);
        wtr_k<<<dim3(32, 16, 1),  blk>>>(w2,    pWch + WOFF_W2,    512, 1024);
    }
    const __half* qkvT  = pWch + WOFF_QKV;
    const __half* projT = pWch + WOFF_PROJ;
    const __half* m1T   = pWch + WOFF_M1;
    const __half* m2T   = pWch + WOFF_M2;
    const __half* w2T   = pWch + WOFF_W2;

    compact_k<<<NBATCH, 256>>>(mask);
    qpe_k<<<1024, 256>>>(gauss);
    pembed_k<<<dim3(GPTS, NBATCH), 256>>>(depth, gauss, w1, b1);

    // prompt features: Pft = Hp @ w2 + b2 (rows = g_M[b]) -> fp32 (feeds X)
    gemm_h<0,false,false><<<dim3(8, 18, NBATCH), 256>>>(
        pHph, (long long)GPTS*512, 0, 512,
        w2T, 0, 0, 512,
        pPft, (long long)GPTS*1024, 0, 1024,
        b2, 1, 0, 1024, 512, 2, 0, 0, 1.0f);

    build_x<<<dim3(NMAXT, NBATCH), 256>>>(img, sep);

    for (int i = 0; i < 2; i++) {
        if (i) sep_rep<<<NBATCH, 256>>>(sep + (size_t)i*1024);

        ln_k<<<dim3(NMAXT, NBATCH), 256>>>(pX, pYh, ln1w + i*1024, ln1b + i*1024);

        // QKV = Y @ qkv_w + qkv_b  -> half
        gemm_h<0,false,true><<<dim3(24, 27, NBATCH), 256>>>(
            pYh, SX, 0, 1024,
            qkvT + (size_t)i*3072*1024, 0, 0, 1024,
            pQKVh, SQKV, 0, 3072,
            qkvb + (size_t)i*3072, 1, 0, 3072, 1024, 1, 0, 0, 1.0f);

        // V transpose for S@V B-operand
        vtr_k<<<dim3(105, 32, NBATCH), dim3(32, 8)>>>(pQKVh, pVt);

        // S = Q K^T / 16 -> half logits, f16 accumulation (2x mma rate)
        gemm_hh<<<dim3(27, 27, NBATCH*4), 256>>>(
            pQKVh, SQKV, 256, 3072,
            pQKVh + 1024, SQKV, 256, 3072,
            pSh, SSB, SS1, SLD,
            4, 0.0625f);

        softmax_k<<<dim3(NMAXT, NBATCH*4), 256>>>();

        // O = Sh @ Vt^T -> Yh half (per-head column slice), f32 acc
        gemm_h<0,false,true><<<dim3(2, 27, NBATCH*4), 256>>>(
            pSh, SSB, SS1, SLD,
            pVt, (long long)1024*NPAD, (long long)256*NPAD, NPAD,
            pYh, SX, 256, 1024,
            nullptr, 4, 0, 256, 0, 1, 0, 1, 1.0f);

        // X += O @ proj_w + proj_b  (residual fp32)
        gemm_h<0,true,false><<<dim3(8, 27, NBATCH), 256>>>(
            pYh, SX, 0, 1024,
            projT + (size_t)i*1024*1024, 0, 0, 1024,
            pX, SX, 0, 1024,
            projb + (size_t)i*1024, 1, 0, 1024, 1024, 1, 0, 0, 1.0f);

        ln_k<<<dim3(NMAXT, NBATCH), 256>>>(pX, pYh, ln2w + i*1024, ln2b + i*1024);

        // H = gelu(Y @ mlp_w1 + mlp_b1) -> half
        gemm_h<1,false,true><<<dim3(32, 27, NBATCH), 256>>>(
            pYh, SX, 0, 1024,
            m1T + (size_t)i*4096*1024, 0, 0, 1024,
            pHh, SH, 0, 4096,
            m1b + (size_t)i*4096, 1, 0, 4096, 1024, 1, 0, 0, 1.0f);

        // X += H @ mlp_w2 + mlp_b2  (residual fp32)
        gemm_h<0,true,false><<<dim3(8, 27, NBATCH), 256>>>(
            pHh, SH, 0, 4096,
            m2T + (size_t)i*1024*4096, 0, 0, 4096,
            pX, SX, 0, 1024,
            m2b + (size_t)i*1024, 1, 0, 1024, 4096, 1, 0, 0, 1.0f);
    }

    out_k<<<dim3(1024, NBATCH), 256>>>(img, out);
}

// round 17
// speedup vs baseline: 1.0878x; 1.0296x over previous
#include <cuda_runtime.h>
#include <cuda_fp16.h>
#include <math.h>
#include <stdint.h>

#define NMAXT 3329      // 1024 query + 1 sep + 2304 max prompts (logical)
#define NPAD  3344      // token-dim padding
#define SLD   3344      // score-matrix row stride
#define GPTS  2304
#define NBATCH 4

// transposed-half-weight scratch layout (element offsets)
#define WOFF_QKV  0LL                    // 2 x [3072][1024]
#define WOFF_PROJ 6291456LL              // 2 x [1024][1024]
#define WOFF_M1   8388608LL              // 2 x [4096][1024]
#define WOFF_M2   16777216LL             // 2 x [1024][4096]
#define WOFF_W2   25165824LL             // [1024][512]
#define WC_TOTAL  25690112LL

// ---------------- static device scratch (zero-initialized, never freed) ---------
__device__ int    g_M[NBATCH];
__device__ int    g_rows[NBATCH*GPTS];
__device__ int    g_cols[NBATCH*GPTS];
__device__ float  g_X   [(size_t)NBATCH*NPAD*1024];            // residual, fp32
__device__ __half g_Yh  [(size_t)NBATCH*NPAD*1024];            // LN out / attn out
__device__ __half g_QKVh[(size_t)NBATCH*NPAD*3072];            // pad rows stay 0
__device__ __half g_Sh  [(size_t)NBATCH*4*NPAD*SLD];           // logits->probs, pad 0
__device__ __half g_Hh  [(size_t)NBATCH*NPAD*4096];            // MLP hidden
__device__ float  g_Qpe [1024*1024];
__device__ float  g_Ppe [(size_t)NBATCH*GPTS*1024];
__device__ __half g_Hph [(size_t)NBATCH*GPTS*512];
__device__ float  g_Pft [(size_t)NBATCH*GPTS*1024];
__device__ __half g_Wch [WC_TOTAL];

__device__ __forceinline__ float geluf(float x) {
    return 0.5f * x * (1.0f + erff(x * 0.7071067811865475f));
}
__device__ __forceinline__ float warpSum(float v) {
    #pragma unroll
    for (int o = 16; o; o >>= 1) v += __shfl_xor_sync(0xFFFFFFFFu, v, o);
    return v;
}
__device__ __forceinline__ float warpMax(float v) {
    #pragma unroll
    for (int o = 16; o; o >>= 1) v = fmaxf(v, __shfl_xor_sync(0xFFFFFFFFu, v, o));
    return v;
}

// ---------------- weight transpose fp32[K][N] -> half[N][K] ---------------------
__global__ void wtr_k(const float* __restrict__ src, __half* __restrict__ dst,
                      int K, int N) {
    __shared__ float t[32][33];
    src += (size_t)blockIdx.z * K * N;
    dst += (size_t)blockIdx.z * K * N;
    int n0 = blockIdx.x * 32, k0 = blockIdx.y * 32;
    int tx = threadIdx.x, ty = threadIdx.y;
    #pragma unroll
    for (int i = 0; i < 32; i += 8)
        t[ty + i][tx] = src[(size_t)(k0 + ty + i) * N + n0 + tx];
    __syncthreads();
    #pragma unroll
    for (int i = 0; i < 32; i += 8)
        dst[(size_t)(n0 + ty + i) * K + k0 + tx] = __float2half_rn(t[tx][ty + i]);
}

// ------- mask compaction: parallel block scan, order == np.nonzero --------------
__global__ void compact_k(const int* __restrict__ mask) {
    int b = blockIdx.x;
    const int* mb = mask + b * GPTS;
    int tid = threadIdx.x, lane = tid & 31, w = tid >> 5;
    __shared__ int warpTot[8], warpBase[8];

    int flags[9];
    int cnt = 0;
    int base0 = tid * 9;
    #pragma unroll
    for (int j = 0; j < 9; j++) {
        flags[j] = (mb[base0 + j] > 0) ? 1 : 0;
        cnt += flags[j];
    }
    int ws = cnt;
    #pragma unroll
    for (int o = 1; o < 32; o <<= 1) {
        int v = __shfl_up_sync(0xFFFFFFFFu, ws, o);
        if (lane >= o) ws += v;
    }
    if (lane == 31) warpTot[w] = ws;
    __syncthreads();
    if (tid == 0) {
        int acc = 0;
        #pragma unroll
        for (int i = 0; i < 8; i++) { warpBase[i] = acc; acc += warpTot[i]; }
        g_M[b] = acc;
    }
    __syncthreads();
    int pos = warpBase[w] + ws - cnt;
    #pragma unroll
    for (int j = 0; j < 9; j++) {
        if (flags[j]) {
            int idx = base0 + j;
            g_rows[b*GPTS + pos] = idx / 48;
            g_cols[b*GPTS + pos] = idx % 48;
            pos++;
        }
    }
}

// ---------------- query positional encoding -------------------------------------
__global__ void qpe_k(const float* __restrict__ gauss) {
    int t = blockIdx.x;            // t = i*32 + j
    int i = t >> 5, j = t & 31;
    float cx = 2.0f * ((j + 0.5f) / 32.0f) - 1.0f;
    float cy = 2.0f * ((i + 0.5f) / 32.0f) - 1.0f;
    for (int k = threadIdx.x; k < 512; k += 256) {
        float ang = 6.283185307179586f * (cx * gauss[k] + cy * gauss[512 + k]);
        g_Qpe[(size_t)t*1024 + k]       = sinf(ang);
        g_Qpe[(size_t)t*1024 + 512 + k] = cosf(ang);
    }
}

// ------------- prompt PE + depth hidden layer gelu(d*w1+b1) ---------------------
__global__ void pembed_k(const float* __restrict__ depth, const float* __restrict__ gauss,
                         const float* __restrict__ w1, const float* __restrict__ b1) {
    int b = blockIdx.y, j = blockIdx.x;
    if (j >= g_M[b]) return;
    int r = g_rows[b*GPTS + j], c = g_cols[b*GPTS + j];
    float cx = 2.0f * ((c + 0.5f) / 48.0f) - 1.0f;
    float cy = 2.0f * ((r + 0.5f) / 48.0f) - 1.0f;
    float d = depth[b*GPTS + r*48 + c];
    size_t base = (size_t)b*GPTS + j;
    for (int k = threadIdx.x; k < 512; k += 256) {
        float ang = 6.283185307179586f * (cx * gauss[k] + cy * gauss[512 + k]);
        g_Ppe[base*1024 + k]       = sinf(ang);
        g_Ppe[base*1024 + 512 + k] = cosf(ang);
        g_Hph[base*512  + k]       = __float2half_rn(geluf(fmaf(d, w1[k], b1[k])));
    }
}

// ---------------- build residual stream (float4) --------------------------------
__global__ void build_x(const float* __restrict__ img, const float* __restrict__ sep0) {
    int b = blockIdx.y, t = blockIdx.x;
    if (t >= 1025 + g_M[b]) return;
    int c = threadIdx.x;
    float4* x4 = (float4*)(g_X + ((size_t)b*NPAD + t) * 1024);
    if (t < 1024) {
        float4 a = ((const float4*)(img + ((size_t)b*1024 + t) * 1024))[c];
        float4 p = ((const float4*)(g_Qpe + (size_t)t*1024))[c];
        a.x += p.x; a.y += p.y; a.z += p.z; a.w += p.w;
        x4[c] = a;
    } else if (t == 1024) {
        x4[c] = ((const float4*)sep0)[c];
    } else {
        size_t base = (size_t)b*GPTS + (t - 1025);
        float4 a = ((const float4*)(g_Pft + base*1024))[c];
        float4 p = ((const float4*)(g_Ppe + base*1024))[c];
        a.x += p.x; a.y += p.y; a.z += p.z; a.w += p.w;
        x4[c] = a;
    }
}

__global__ void sep_rep(const float* __restrict__ sep1) {
    int b = blockIdx.x;
    float4* x4 = (float4*)(g_X + ((size_t)b*NPAD + 1024) * 1024);
    x4[threadIdx.x] = ((const float4*)sep1)[threadIdx.x];
}

// ---------------- layernorm: fp32 in -> half out --------------------------------
__global__ void ln_k(const float* __restrict__ Xin, __half* __restrict__ Yout,
                     const float* __restrict__ w, const float* __restrict__ bb) {
    int b = blockIdx.y, t = blockIdx.x;
    if (t >= 1025 + g_M[b]) return;
    int tid = threadIdx.x;
    const float4* x4 = (const float4*)(Xin + ((size_t)b*NPAD + t) * 1024);
    float4 v = x4[tid];
    float s  = v.x + v.y + v.z + v.w;
    float sq = v.x*v.x + v.y*v.y + v.z*v.z + v.w*v.w;
    __shared__ float shs[8], shq[8], res[2];
    float ws = warpSum(s), wq = warpSum(sq);
    if ((tid & 31) == 0) { shs[tid>>5] = ws; shq[tid>>5] = wq; }
    __syncthreads();
    if (tid == 0) {
        float a = 0.f, q = 0.f;
        #pragma unroll
        for (int i = 0; i < 8; i++) { a += shs[i]; q += shq[i]; }
        res[0] = a; res[1] = q;
    }
    __syncthreads();
    float mean = res[0] * (1.0f/1024.0f);
    float var  = res[1] * (1.0f/1024.0f) - mean*mean;
    float rstd = rsqrtf(var + 1e-5f);
    float4 wv = ((const float4*)w)[tid];
    float4 bv = ((const float4*)bb)[tid];
    __half2* yrow = (__half2*)(Yout + ((size_t)b*NPAD + t) * 1024);
    yrow[2*tid]   = __floats2half2_rn((v.x - mean)*rstd*wv.x + bv.x,
                                      (v.y - mean)*rstd*wv.y + bv.y);
    yrow[2*tid+1] = __floats2half2_rn((v.z - mean)*rstd*wv.z + bv.z,
                                      (v.w - mean)*rstd*wv.w + bv.w);
}

// ---------------- row softmax: half logits -> half probs, half2 vectorized ------
__global__ void softmax_k() {
    int z = blockIdx.y;            // b*4 + head
    int b = z >> 2;
    int Nd = 1025 + g_M[b];
    int row = blockIdx.x;
    if (row >= Nd) return;
    __half2* sh2 = (__half2*)(g_Sh + (size_t)z*NPAD*SLD + (size_t)row*SLD);
    int tid = threadIdx.x;
    __shared__ float red[8];

    float2 vals[7];
    float m = -3.4e38f;
    #pragma unroll
    for (int t = 0; t < 7; t++) {
        int j2 = tid + t*256;
        int c0 = j2 << 1;
        if (c0 < Nd) {
            float2 v = __half22float2(sh2[j2]);
            vals[t] = v;
            m = fmaxf(m, v.x);
            if (c0 + 1 < Nd) m = fmaxf(m, v.y);
        }
    }
    m = warpMax(m);
    if ((tid & 31) == 0) red[tid>>5] = m;
    __syncthreads();
    if (tid == 0) {
        float v = red[0];
        #pragma unroll
        for (int i = 1; i < 8; i++) v = fmaxf(v, red[i]);
        red[0] = v;
    }
    __syncthreads();
    m = red[0];
    __syncthreads();

    float sum = 0.f;
    #pragma unroll
    for (int t = 0; t < 7; t++) {
        int j2 = tid + t*256;
        int c0 = j2 << 1;
        if (c0 < Nd) {
            float e0 = expf(vals[t].x - m);
            float e1 = (c0 + 1 < Nd) ? expf(vals[t].y - m) : 0.f;
            vals[t].x = e0; vals[t].y = e1;
            sum += e0 + e1;
        }
    }
    sum = warpSum(sum);
    if ((tid & 31) == 0) red[tid>>5] = sum;
    __syncthreads();
    if (tid == 0) {
        float v = 0.f;
        #pragma unroll
        for (int i = 0; i < 8; i++) v += red[i];
        red[0] = v;
    }
    __syncthreads();
    float inv = 1.0f / red[0];
    #pragma unroll
    for (int t = 0; t < 7; t++) {
        int j2 = tid + t*256;
        int c0 = j2 << 1;
        if (c0 + 1 < Nd) {
            sh2[j2] = __floats2half2_rn(vals[t].x * inv, vals[t].y * inv);
        } else if (c0 < Nd) {
            ((__half*)sh2)[c0] = __float2half_rn(vals[t].x * inv);
        }
    }
}

// ================= shared GEMM helpers ==========================================
__device__ __forceinline__ int dimval(int st, int dyn, int b) {
    if (dyn == 1) return 1025 + g_M[b];
    if (dyn == 2) return g_M[b];
    return st;
}
__device__ __forceinline__ void cpa16(uint32_t dst, const void* src, int srcBytes) {
    asm volatile("cp.async.cg.shared.global [%0], [%1], 16, %2;"
                 :: "r"(dst), "l"(src), "r"(srcBytes));
}
#define MMA_F16(d, a, bq)                                                \
    asm volatile("mma.sync.aligned.m16n8k16.row.col.f32.f16.f16.f32 "    \
        "{%0,%1,%2,%3},{%4,%5,%6,%7},{%8,%9},{%0,%1,%2,%3};"             \
        : "+f"(d[0]),"+f"(d[1]),"+f"(d[2]),"+f"(d[3])                    \
        : "r"(a[0]),"r"(a[1]),"r"(a[2]),"r"(a[3]),"r"(bq[0]),"r"(bq[1]))
#define MMA_F16H(d, a, bq)                                               \
    asm volatile("mma.sync.aligned.m16n8k16.row.col.f16.f16.f16.f16 "    \
        "{%0,%1},{%2,%3,%4,%5},{%6,%7},{%0,%1};"                         \
        : "+r"(d[0]),"+r"(d[1])                                          \
        : "r"(a[0]),"r"(a[1]),"r"(a[2]),"r"(a[3]),"r"(bq[0]),"r"(bq[1]))
#define LDSM4(r0, r1, r2, r3, addr)                                      \
    asm volatile("ldmatrix.sync.aligned.m8n8.x4.shared.b16 "             \
        "{%0,%1,%2,%3}, [%4];"                                           \
        : "=r"(r0), "=r"(r1), "=r"(r2), "=r"(r3) : "r"(addr))
#define LDSM2(r0, r1, addr)                                              \
    asm volatile("ldmatrix.sync.aligned.m8n8.x2.shared.b16 "             \
        "{%0,%1}, [%2];"                                                 \
        : "=r"(r0), "=r"(r1) : "r"(addr))
#define LDSM2T(r0, r1, addr)                                             \
    asm volatile("ldmatrix.sync.aligned.m8n8.x2.trans.shared.b16 "       \
        "{%0,%1}, [%2];"                                                 \
        : "=r"(r0), "=r"(r1) : "r"(addr))

// =========================== fp16 tensor-core GEMM (f32 acc) ====================
template<int EPI, bool ACCUM, bool OUTH>
__global__ void __launch_bounds__(256, 2) gemm_h(
    const __half* __restrict__ A, long long aOut, long long aIn, int lda,
    const __half* __restrict__ B, long long bOut, long long bIn, int ldb,
    void* __restrict__ Cv, long long cOut, long long cIn, int ldc,
    const float* __restrict__ bias,
    int nInner, int Mst, int Nst, int Kst,
    int dynM, int dynN, int dynK, float alpha)
{
    int z = blockIdx.z;
    int b = z / nInner, ii = z - b*nInner;
    int Mr = dimval(Mst, dynM, b);
    int Nc = dimval(Nst, dynN, b);
    int K  = dimval(Kst, dynK, b);
    int Kpad = (K + 31) & ~31;
    int m0 = blockIdx.y * 128, n0 = blockIdx.x * 128;
    if (m0 >= Mr || n0 >= Nc) return;
    A += b*aOut + ii*aIn;
    B += b*bOut + ii*bIn;

    __shared__ __align__(16) uint32_t Asm[2*2560];
    __shared__ __align__(16) uint32_t Bsm[2*2560];
    uint32_t sA = (uint32_t)__cvta_generic_to_shared(Asm);
    uint32_t sB = (uint32_t)__cvta_generic_to_shared(Bsm);

    int tid  = threadIdx.x;
    int wid  = tid >> 5, lane = tid & 31;
    int wm   = (wid >> 2) * 64;
    int wn   = (wid & 3) * 32;
    int g    = lane >> 2, t4 = lane & 3;

    float acc[4][4][4];
    #pragma unroll
    for (int i = 0; i < 4; i++)
        #pragma unroll
        for (int j = 0; j < 4; j++)
            #pragma unroll
            for (int e = 0; e < 4; e++) acc[i][j][e] = 0.f;

    auto issue = [&](int kt, int buf) {
        int k0 = kt << 5;
        #pragma unroll
        for (int i = 0; i < 2; i++) {
            int idx = tid + 256*i;
            int r = idx >> 2, cw = (idx & 3) << 2;
            int gm = m0 + r;
            bool ok = gm < Mr;
            const __half* src = ok ? (A + (long long)gm*lda + k0 + (cw<<1)) : A;
            cpa16(sA + (uint32_t)(buf*2560 + r*20 + cw)*4, src, ok ? 16 : 0);
        }
        #pragma unroll
        for (int i = 0; i < 2; i++) {
            int idx = tid + 256*i;
            int r = idx >> 2, cw = (idx & 3) << 2;
            int gn = n0 + r;
            bool ok = gn < Nc;
            const __half* src = ok ? (B + (long long)gn*ldb + k0 + (cw<<1)) : B;
            cpa16(sB + (uint32_t)(buf*2560 + r*20 + cw)*4, src, ok ? 16 : 0);
        }
    };

    int lane16 = lane & 15;
    int laneh  = lane >> 4;
    int lane8  = lane & 7;
    int laneb  = (lane >> 3) & 1;

    auto compute = [&](int buf) {
        uint32_t aBase = sA + (uint32_t)(buf*2560 + (wm + lane16)*20 + laneh*4)*4;
        uint32_t bBase = sB + (uint32_t)(buf*2560 + (wn + lane8 )*20 + laneb*4)*4;
        #pragma unroll
        for (int ks = 0; ks < 2; ks++) {
            uint32_t kOff = (uint32_t)(ks*8)*4;
            uint32_t af[4][4], bf[4][2];
            #pragma unroll
            for (int mf = 0; mf < 4; mf++)
                LDSM4(af[mf][0], af[mf][1], af[mf][2], af[mf][3],
                      aBase + (uint32_t)(mf*16*20)*4 + kOff);
            #pragma unroll
            for (int nf = 0; nf < 4; nf++)
                LDSM2(bf[nf][0], bf[nf][1],
                      bBase + (uint32_t)(nf*8*20)*4 + kOff);
            #pragma unroll
            for (int mf = 0; mf < 4; mf++)
                #pragma unroll
                for (int nf = 0; nf < 4; nf++)
                    MMA_F16(acc[mf][nf], af[mf], bf[nf]);
        }
    };

    int ntiles = Kpad >> 5;
    issue(0, 0);
    asm volatile("cp.async.commit_group;" ::: "memory");
    for (int it = 0; it < ntiles; it++) {
        if (it + 1 < ntiles) issue(it + 1, (it + 1) & 1);
        asm volatile("cp.async.commit_group;" ::: "memory");
        asm volatile("cp.async.wait_group 1;" ::: "memory");
        __syncthreads();
        compute(it & 1);
        __syncthreads();
    }

    float*  Cf = (float*) Cv;
    __half* Ch = (__half*)Cv;
    long long cbase = b*cOut + ii*cIn;
    #pragma unroll
    for (int mf = 0; mf < 4; mf++) {
        #pragma unroll
        for (int nf = 0; nf < 4; nf++) {
            int gn0 = n0 + wn + nf*8 + 2*t4;
            #pragma unroll
            for (int rr = 0; rr < 2; rr++) {
                int gm = m0 + wm + mf*16 + g + rr*8;
                if (gm >= Mr) continue;
                float v0 = acc[mf][nf][2*rr    ] * alpha;
                float v1 = acc[mf][nf][2*rr + 1] * alpha;
                if (bias) { v0 += bias[gn0]; v1 += bias[gn0 + 1]; }
                if (EPI == 1) { v0 = geluf(v0); v1 = geluf(v1); }
                long long off = cbase + (long long)gm*ldc + gn0;
                if (OUTH) {
                    if (gn0 + 1 < Nc)
                        *(__half2*)(Ch + off) = __floats2half2_rn(v0, v1);
                    else if (gn0 < Nc)
                        Ch[off] = __float2half_rn(v0);
                } else {
                    if (gn0 < Nc)     { if (ACCUM) Cf[off]   += v0; else Cf[off]   = v0; }
                    if (gn0 + 1 < Nc) { if (ACCUM) Cf[off+1] += v1; else Cf[off+1] = v1; }
                }
            }
        }
    }
}

// ================== fp16 tensor-core GEMM, f16 accumulation (QK only) ===========
__global__ void __launch_bounds__(256, 2) gemm_hh(
    const __half* __restrict__ A, long long aOut, long long aIn, int lda,
    const __half* __restrict__ B, long long bOut, long long bIn, int ldb,
    __half* __restrict__ C, long long cOut, long long cIn, int ldc,
    int nInner, float alpha)
{
    int z = blockIdx.z;
    int b = z / nInner, ii = z - b*nInner;
    int Mr = 1025 + g_M[b];
    int Nc = Mr;
    int m0 = blockIdx.y * 128, n0 = blockIdx.x * 128;
    if (m0 >= Mr || n0 >= Nc) return;
    A += b*aOut + ii*aIn;
    B += b*bOut + ii*bIn;

    __shared__ __align__(16) uint32_t Asm[2*2560];
    __shared__ __align__(16) uint32_t Bsm[2*2560];
    uint32_t sA = (uint32_t)__cvta_generic_to_shared(Asm);
    uint32_t sB = (uint32_t)__cvta_generic_to_shared(Bsm);

    int tid  = threadIdx.x;
    int wid  = tid >> 5, lane = tid & 31;
    int wm   = (wid >> 2) * 64;
    int wn   = (wid & 3) * 32;
    int g    = lane >> 2, t4 = lane & 3;

    uint32_t acc[4][4][2];
    #pragma unroll
    for (int i = 0; i < 4; i++)
        #pragma unroll
        for (int j = 0; j < 4; j++) { acc[i][j][0] = 0u; acc[i][j][1] = 0u; }

    auto issue = [&](int kt, int buf) {
        int k0 = kt << 5;
        #pragma unroll
        for (int i = 0; i < 2; i++) {
            int idx = tid + 256*i;
            int r = idx >> 2, cw = (idx & 3) << 2;
            int gm = m0 + r;
            bool ok = gm < Mr;
            const __half* src = ok ? (A + (long long)gm*lda + k0 + (cw<<1)) : A;
            cpa16(sA + (uint32_t)(buf*2560 + r*20 + cw)*4, src, ok ? 16 : 0);
        }
        #pragma unroll
        for (int i = 0; i < 2; i++) {
            int idx = tid + 256*i;
            int r = idx >> 2, cw = (idx & 3) << 2;
            int gn = n0 + r;
            bool ok = gn < Nc;
            const __half* src = ok ? (B + (long long)gn*ldb + k0 + (cw<<1)) : B;
            cpa16(sB + (uint32_t)(buf*2560 + r*20 + cw)*4, src, ok ? 16 : 0);
        }
    };

    int lane16 = lane & 15;
    int laneh  = lane >> 4;
    int lane8  = lane & 7;
    int laneb  = (lane >> 3) & 1;

    auto compute = [&](int buf) {
        uint32_t aBase = sA + (uint32_t)(buf*2560 + (wm + lane16)*20 + laneh*4)*4;
        uint32_t bBase = sB + (uint32_t)(buf*2560 + (wn + lane8 )*20 + laneb*4)*4;
        #pragma unroll
        for (int ks = 0; ks < 2; ks++) {
            uint32_t kOff = (uint32_t)(ks*8)*4;
            uint32_t af[4][4], bf[4][2];
            #pragma unroll
            for (int mf = 0; mf < 4; mf++)
                LDSM4(af[mf][0], af[mf][1], af[mf][2], af[mf][3],
                      aBase + (uint32_t)(mf*16*20)*4 + kOff);
            #pragma unroll
            for (int nf = 0; nf < 4; nf++)
                LDSM2(bf[nf][0], bf[nf][1],
                      bBase + (uint32_t)(nf*8*20)*4 + kOff);
            #pragma unroll
            for (int mf = 0; mf < 4; mf++)
                #pragma unroll
                for (int nf = 0; nf < 4; nf++)
                    MMA_F16H(acc[mf][nf], af[mf], bf[nf]);
        }
    };

    int ntiles = 8;                 // K=256 fixed
    issue(0, 0);
    asm volatile("cp.async.commit_group;" ::: "memory");
    for (int it = 0; it < ntiles; it++) {
        if (it + 1 < ntiles) issue(it + 1, (it + 1) & 1);
        asm volatile("cp.async.commit_group;" ::: "memory");
        asm volatile("cp.async.wait_group 1;" ::: "memory");
        __syncthreads();
        compute(it & 1);
        __syncthreads();
    }

    long long cbase = b*cOut + ii*cIn;
    #pragma unroll
    for (int mf = 0; mf < 4; mf++) {
        #pragma unroll
        for (int nf = 0; nf < 4; nf++) {
            int gn0 = n0 + wn + nf*8 + 2*t4;
            #pragma unroll
            for (int rr = 0; rr < 2; rr++) {
                int gm = m0 + wm + mf*16 + g + rr*8;
                if (gm >= Mr) continue;
                float2 vv = __half22float2(*(__half2*)&acc[mf][nf][rr]);
                float v0 = vv.x * alpha;
                float v1 = vv.y * alpha;
                long long off = cbase + (long long)gm*ldc + gn0;
                if (gn0 + 1 < Nc)
                    *(__half2*)(C + off) = __floats2half2_rn(v0, v1);
                else if (gn0 < Nc)
                    C[off] = __float2half_rn(v0);
            }
        }
    }
}

// ============ S@V GEMM: B read from V[tok][dim] via ldmatrix.trans ==============
// C(half) = A(Sh probs) @ V ; A: [m=tok_q][k=tok_kv], B smem: [k=32 tok][n=128 dim].
__global__ void __launch_bounds__(256, 2) gemm_sv(
    const __half* __restrict__ A, long long aOut, long long aIn, int lda,
    const __half* __restrict__ Bv, long long bOut, long long bIn, int ldb,
    __half* __restrict__ C, long long cOut, long long cIn, int ldc)
{
    int z = blockIdx.z;
    int b = z >> 2, h = z & 3;
    int Mr = 1025 + g_M[b];
    int K  = Mr;
    int Kpad = (K + 31) & ~31;
    int m0 = blockIdx.y * 128, n0 = blockIdx.x * 128;
    if (m0 >= Mr) return;
    A  += b*aOut + h*aIn;
    Bv += b*bOut + h*bIn;

    __shared__ __align__(16) uint32_t Asm[2*2560];
    __shared__ __align__(16) uint32_t Bsm[2*2176];   // 32 k-rows x 68 words/row
    uint32_t sA = (uint32_t)__cvta_generic_to_shared(Asm);
    uint32_t sB = (uint32_t)__cvta_generic_to_shared(Bsm);

    int tid  = threadIdx.x;
    int wid  = tid >> 5, lane = tid & 31;
    int wm   = (wid >> 2) * 64;
    int wn   = (wid & 3) * 32;
    int g    = lane >> 2, t4 = lane & 3;

    float acc[4][4][4];
    #pragma unroll
    for (int i = 0; i < 4; i++)
        #pragma unroll
        for (int j = 0; j < 4; j++)
            #pragma unroll
            for (int e = 0; e < 4; e++) acc[i][j][e] = 0.f;

    auto issue = [&](int kt, int buf) {
        int k0 = kt << 5;
        // A: 128 m-rows x 32 k-halves (stride 20 words)
        #pragma unroll
        for (int i = 0; i < 2; i++) {
            int idx = tid + 256*i;
            int r = idx >> 2, cw = (idx & 3) << 2;
            int gm = m0 + r;
            bool ok = gm < Mr;
            const __half* src = ok ? (A + (long long)gm*lda + k0 + (cw<<1)) : A;
            cpa16(sA + (uint32_t)(buf*2560 + r*20 + cw)*4, src, ok ? 16 : 0);
        }
        // B: 32 k-rows (tok) x 128 n-halves (dim), stride 68 words
        #pragma unroll
        for (int i = 0; i < 2; i++) {
            int idx = tid + 256*i;
            int r = idx >> 4, c = idx & 15;       // r: tok row, c: 16B chunk
            int tok = k0 + r;
            bool ok = tok < NPAD;                 // pad rows valid zeros
            const __half* src = ok ? (Bv + (long long)tok*ldb + n0 + c*8) : Bv;
            cpa16(sB + (uint32_t)(buf*2176 + r*68 + c*4)*4, src, ok ? 16 : 0);
        }
    };

    int lane16 = lane & 15;
    int laneh  = lane >> 4;
    int lane8  = lane & 7;
    int laneb  = (lane >> 3) & 1;

    auto compute = [&](int buf) {
        uint32_t aBase = sA + (uint32_t)(buf*2560 + (wm + lane16)*20 + laneh*4)*4;
        // B trans: lanes 0-7 -> k rows kk+lane8 (matrix0), 8-15 -> kk+8+lane8 (matrix1)
        uint32_t bBase = sB + (uint32_t)(buf*2176 + (lane8 + 8*laneb)*68 + (wn >> 1))*4;
        #pragma unroll
        for (int ks = 0; ks < 2; ks++) {
            uint32_t kOffA = (uint32_t)(ks*8)*4;
            uint32_t kOffB = (uint32_t)(ks*16*68)*4;
            uint32_t af[4][4], bf[4][2];
            #pragma unroll
            for (int mf = 0; mf < 4; mf++)
                LDSM4(af[mf][0], af[mf][1], af[mf][2], af[mf][3],
                      aBase + (uint32_t)(mf*16*20)*4 + kOffA);
            #pragma unroll
            for (int nf = 0; nf < 4; nf++)
                LDSM2T(bf[nf][0], bf[nf][1],
                       bBase + kOffB + (uint32_t)(nf*4)*4);
            #pragma unroll
            for (int mf = 0; mf < 4; mf++)
                #pragma unroll
                for (int nf = 0; nf < 4; nf++)
                    MMA_F16(acc[mf][nf], af[mf], bf[nf]);
        }
    };

    int ntiles = Kpad >> 5;
    issue(0, 0);
    asm volatile("cp.async.commit_group;" ::: "memory");
    for (int it = 0; it < ntiles; it++) {
        if (it + 1 < ntiles) issue(it + 1, (it + 1) & 1);
        asm volatile("cp.async.commit_group;" ::: "memory");
        asm volatile("cp.async.wait_group 1;" ::: "memory");
        __syncthreads();
        compute(it & 1);
        __syncthreads();
    }

    long long cbase = b*cOut + h*cIn;
    #pragma unroll
    for (int mf = 0; mf < 4; mf++) {
        #pragma unroll
        for (int nf = 0; nf < 4; nf++) {
            int gn0 = n0 + wn + nf*8 + 2*t4;      // < 256 always (128 cols/tile)
            #pragma unroll
            for (int rr = 0; rr < 2; rr++) {
                int gm = m0 + wm + mf*16 + g + rr*8;
                if (gm >= Mr) continue;
                long long off = cbase + (long long)gm*ldc + gn0;
                *(__half2*)(C + off) =
                    __floats2half2_rn(acc[mf][nf][2*rr], acc[mf][nf][2*rr + 1]);
            }
        }
    }
}

// ---------------- output (float4) ------------------------------------------------
__global__ void out_k(const float* __restrict__ img, float* __restrict__ out) {
    int b = blockIdx.y, t = blockIdx.x;
    const float4* src = (g_M[b] == 0)
        ? (const float4*)(img + ((size_t)b*1024 + t) * 1024)
        : (const float4*)(g_X + ((size_t)b*NPAD + t) * 1024);
    float4* o = (float4*)(out + ((size_t)b*1024 + t) * 1024);
    o[threadIdx.x] = src[threadIdx.x];
}

// ================================ host ==========================================
extern "C" void kernel_launch(void* const* d_in, const int* in_sizes, int n_in,
                              void* d_out, int out_size) {
    const float* img   = (const float*)d_in[0];
    const float* depth = (const float*)d_in[1];
    const int*   mask  = (const int*)  d_in[2];
    const float* gauss = (const float*)d_in[5];
    const float* w1    = (const float*)d_in[6];
    const float* b1    = (const float*)d_in[7];
    const float* w2    = (const float*)d_in[8];
    const float* b2    = (const float*)d_in[9];
    const float* sep   = (const float*)d_in[10];
    const float* ln1w  = (const float*)d_in[11];
    const float* ln1b  = (const float*)d_in[12];
    const float* qkvw  = (const float*)d_in[13];
    const float* qkvb  = (const float*)d_in[14];
    const float* projw = (const float*)d_in[15];
    const float* projb = (const float*)d_in[16];
    const float* ln2w  = (const float*)d_in[17];
    const float* ln2b  = (const float*)d_in[18];
    const float* m1w   = (const float*)d_in[19];
    const float* m1b   = (const float*)d_in[20];
    const float* m2w   = (const float*)d_in[21];
    const float* m2b   = (const float*)d_in[22];
    float* out = (float*)d_out;

    float *pX, *pPft;
    __half *pYh, *pQKVh, *pSh, *pHh, *pHph, *pWch;
    cudaGetSymbolAddress((void**)&pX,    g_X);
    cudaGetSymbolAddress((void**)&pPft,  g_Pft);
    cudaGetSymbolAddress((void**)&pYh,   g_Yh);
    cudaGetSymbolAddress((void**)&pQKVh, g_QKVh);
    cudaGetSymbolAddress((void**)&pSh,   g_Sh);
    cudaGetSymbolAddress((void**)&pHh,   g_Hh);
    cudaGetSymbolAddress((void**)&pHph,  g_Hph);
    cudaGetSymbolAddress((void**)&pWch,  g_Wch);

    const long long SX   = (long long)NPAD * 1024;
    const long long SQKV = (long long)NPAD * 3072;
    const long long SH   = (long long)NPAD * 4096;
    const long long SS1  = (long long)NPAD * SLD;    // per head
    const long long SSB  = 4LL * SS1;                // per batch

    // --- transpose+round all GEMM weights to half [N][K] once per call ---
    {
        dim3 blk(32, 8);
        wtr_k<<<dim3(96, 32, 2),  blk>>>(qkvw,  pWch + WOFF_QKV,  1024, 3072);
        wtr_k<<<dim3(32, 32, 2),  blk>>>(projw, pWch + WOFF_PROJ, 1024, 1024);
        wtr_k<<<dim3(128, 32, 2), blk>>>(m1w,   pWch + WOFF_M1,   1024, 4096);
        wtr_k<<<dim3(32, 128, 2), blk>>>(m2w,   pWch + WOFF_M2,   4096, 1024);
        wtr_k<<<dim3(32, 16, 1),  blk>>>(w2,    pWch + WOFF_W2,    512, 1024);
    }
    const __half* qkvT  = pWch + WOFF_QKV;
    const __half* projT = pWch + WOFF_PROJ;
    const __half* m1T   = pWch + WOFF_M1;
    const __half* m2T   = pWch + WOFF_M2;
    const __half* w2T   = pWch + WOFF_W2;

    compact_k<<<NBATCH, 256>>>(mask);
    qpe_k<<<1024, 256>>>(gauss);
    pembed_k<<<dim3(GPTS, NBATCH), 256>>>(depth, gauss, w1, b1);

    // prompt features: Pft = Hp @ w2 + b2 (rows = g_M[b]) -> fp32 (feeds X)
    gemm_h<0,false,false><<<dim3(8, 18, NBATCH), 256>>>(
        pHph, (long long)GPTS*512, 0, 512,
        w2T, 0, 0, 512,
        pPft, (long long)GPTS*1024, 0, 1024,
        b2, 1, 0, 1024, 512, 2, 0, 0, 1.0f);

    build_x<<<dim3(NMAXT, NBATCH), 256>>>(img, sep);

    for (int i = 0; i < 2; i++) {
        if (i) sep_rep<<<NBATCH, 256>>>(sep + (size_t)i*1024);

        ln_k<<<dim3(NMAXT, NBATCH), 256>>>(pX, pYh, ln1w + i*1024, ln1b + i*1024);

        // QKV = Y @ qkv_w + qkv_b  -> half
        gemm_h<0,false,true><<<dim3(24, 27, NBATCH), 256>>>(
            pYh, SX, 0, 1024,
            qkvT + (size_t)i*3072*1024, 0, 0, 1024,
            pQKVh, SQKV, 0, 3072,
            qkvb + (size_t)i*3072, 1, 0, 3072, 1024, 1, 0, 0, 1.0f);

        // S = Q K^T / 16 -> half logits, f16 accumulation
        gemm_hh<<<dim3(27, 27, NBATCH*4), 256>>>(
            pQKVh, SQKV, 256, 3072,
            pQKVh + 1024, SQKV, 256, 3072,
            pSh, SSB, SS1, SLD,
            4, 0.0625f);

        softmax_k<<<dim3(NMAXT, NBATCH*4), 256>>>();

        // O = Sh @ V -> Yh (V read in [tok][dim] layout via ldmatrix.trans)
        gemm_sv<<<dim3(2, 27, NBATCH*4), 256>>>(
            pSh, SSB, SS1, SLD,
            pQKVh + 2048, SQKV, 256, 3072,
            pYh, SX, 256, 1024);

        // X += O @ proj_w + proj_b  (residual fp32)
        gemm_h<0,true,false><<<dim3(8, 27, NBATCH), 256>>>(
            pYh, SX, 0, 1024,
            projT + (size_t)i*1024*1024, 0, 0, 1024,
            pX, SX, 0, 1024,
            projb + (size_t)i*1024, 1, 0, 1024, 1024, 1, 0, 0, 1.0f);

        ln_k<<<dim3(NMAXT, NBATCH), 256>>>(pX, pYh, ln2w + i*1024, ln2b + i*1024);

        // H = gelu(Y @ mlp_w1 + mlp_b1) -> half
        gemm_h<1,false,true><<<dim3(32, 27, NBATCH), 256>>>(
            pYh, SX, 0, 1024,
            m1T + (size_t)i*4096*1024, 0, 0, 1024,
            pHh, SH, 0, 4096,
            m1b + (size_t)i*4096, 1, 0, 4096, 1024, 1, 0, 0, 1.0f);

        // X += H @ mlp_w2 + mlp_b2  (residual fp32)
        gemm_h<0,true,false><<<dim3(8, 27, NBATCH), 256>>>(
            pHh, SH, 0, 4096,
            m2T + (size_t)i*1024*4096, 0, 0, 4096,
            pX, SX, 0, 1024,
            m2b + (size_t)i*1024, 1, 0, 1024, 4096, 1, 0, 0, 1.0f);
    }

    out_k<<<dim3(1024, NBATCH), 256>>>(img, out);
}